// round 1
// baseline (speedup 1.0000x reference)
#include <cuda_runtime.h>
#include <math.h>

// Problem constants
#define SQ   2048
#define NH   16
#define DHH  64
#define DD   1024
#define BB   2
#define MTOK 4096   // B*S tokens

// Scratch (device globals — no allocation allowed)
__device__ float g_qkv[(size_t)MTOK * 3072];  // 48 MB: (token, [3][H][DH])
__device__ float g_att[(size_t)MTOK * DD];    // 16 MB: (token, H*DH)

// ============================================================
// SGEMM: C(MxN) = A(MxK) * B(KxN), all row-major fp32.
// 128x128 tile, BK=8, 8x8 per-thread microtile, 256 threads.
// M,N,K must be multiples of 128/128/8 (they are here).
// ============================================================
__global__ __launch_bounds__(256) void sgemm_kernel(
    const float* __restrict__ A, const float* __restrict__ B,
    float* __restrict__ C, int M, int N, int K)
{
    const int BM = 128, BN = 128, BK = 8;
    __shared__ __align__(16) float As[BK * BM];   // transposed: As[k][m]
    __shared__ __align__(16) float Bs[BK * BN];   // Bs[k][n]

    int tid  = threadIdx.x;
    int row0 = blockIdx.y * BM;
    int col0 = blockIdx.x * BN;

    int irA = tid >> 1;          // 0..127
    int icA = (tid & 1) * 4;     // 0 or 4
    int irB = tid >> 5;          // 0..7
    int icB = (tid & 31) * 4;    // 0..124

    int tr = (tid >> 4) * 8;     // microtile row offset
    int tc = (tid & 15) * 8;     // microtile col offset

    const float* Aptr = A + (size_t)(row0 + irA) * K + icA;
    const float* Bptr = B + (size_t)irB * N + col0 + icB;

    float acc[8][8];
    #pragma unroll
    for (int i = 0; i < 8; i++)
        #pragma unroll
        for (int j = 0; j < 8; j++) acc[i][j] = 0.0f;

    for (int k0 = 0; k0 < K; k0 += BK) {
        float4 a4 = *(const float4*)(Aptr + k0);
        As[(icA + 0) * BM + irA] = a4.x;
        As[(icA + 1) * BM + irA] = a4.y;
        As[(icA + 2) * BM + irA] = a4.z;
        As[(icA + 3) * BM + irA] = a4.w;
        float4 b4 = *(const float4*)(Bptr + (size_t)k0 * N);
        *(float4*)(&Bs[irB * BN + icB]) = b4;
        __syncthreads();

        #pragma unroll
        for (int k = 0; k < BK; k++) {
            float ra[8], rb[8];
            float4 t0 = *(const float4*)(&As[k * BM + tr]);
            float4 t1 = *(const float4*)(&As[k * BM + tr + 4]);
            ra[0]=t0.x; ra[1]=t0.y; ra[2]=t0.z; ra[3]=t0.w;
            ra[4]=t1.x; ra[5]=t1.y; ra[6]=t1.z; ra[7]=t1.w;
            float4 u0 = *(const float4*)(&Bs[k * BN + tc]);
            float4 u1 = *(const float4*)(&Bs[k * BN + tc + 4]);
            rb[0]=u0.x; rb[1]=u0.y; rb[2]=u0.z; rb[3]=u0.w;
            rb[4]=u1.x; rb[5]=u1.y; rb[6]=u1.z; rb[7]=u1.w;
            #pragma unroll
            for (int i = 0; i < 8; i++)
                #pragma unroll
                for (int j = 0; j < 8; j++)
                    acc[i][j] = fmaf(ra[i], rb[j], acc[i][j]);
        }
        __syncthreads();
    }

    #pragma unroll
    for (int i = 0; i < 8; i++) {
        float* crow = C + (size_t)(row0 + tr + i) * N + col0 + tc;
        float4 v0 = make_float4(acc[i][0], acc[i][1], acc[i][2], acc[i][3]);
        float4 v1 = make_float4(acc[i][4], acc[i][5], acc[i][6], acc[i][7]);
        *(float4*)(crow)     = v0;
        *(float4*)(crow + 4) = v1;
    }
}

// ============================================================
// Banded attention: causal ∧ |i-j|<=128 band. Per block:
// one (b, h, 64-row q-tile). Keys window = [q0-128, q0+63] (192 keys).
// Exact softmax over the band (masked entries underflow to 0, matching
// the reference's additive -1e9 masks).
// ============================================================
#define QT   64
#define KT   192
#define QTP  65     // Qs row pitch
#define KTP  193    // Ks row pitch
#define DHP  65     // Vs row pitch
#define PSP  196    // Ps row pitch

#define ATTN_SMEM ((DHH*QTP + DHH*KTP + KT*DHP + QT*PSP) * sizeof(float))

__global__ __launch_bounds__(256) void attn_kernel(
    const float* __restrict__ traj, float* __restrict__ att_out)
{
    extern __shared__ float sm[];
    float* Qs = sm;                       // [DHH][QTP]  Qs[d][r]
    float* Ks = Qs + DHH * QTP;           // [DHH][KTP]  Ks[d][k]
    float* Vs = Ks + DHH * KTP;           // [KT][DHP]   Vs[k][d]
    float* Ps = Vs + KT * DHP;            // [QT][PSP]   scores/probs

    const int tid = threadIdx.x;
    const int b = blockIdx.z, h = blockIdx.y;
    const int q0 = blockIdx.x * QT;
    const int k0 = q0 - 128;
    const float NEGINF = __int_as_float(0xff800000);

    const float* qkbase = g_qkv + (size_t)b * SQ * 3072;

    // Load Q (coalesced over dh)
    for (int idx = tid; idx < QT * DHH; idx += 256) {
        int d = idx & 63, r = idx >> 6;
        Qs[d * QTP + r] = qkbase[(size_t)(q0 + r) * 3072 + h * 64 + d];
    }
    // Load K and V (coalesced over dh); out-of-range keys -> 0
    for (int idx = tid; idx < KT * DHH; idx += 256) {
        int d = idx & 63, kk = idx >> 6;
        int key = k0 + kk;
        float kv = 0.0f, vv = 0.0f;
        if (key >= 0) {
            const float* p = qkbase + (size_t)key * 3072 + 1024 + h * 64 + d;
            kv = p[0];
            vv = p[1024];
        }
        Ks[d * KTP + kk] = kv;
        Vs[kk * DHP + d] = vv;
    }
    __syncthreads();

    // ---- Scores: 64x192, microtile 8 rows x 6 cols per thread ----
    const int tcg = tid & 31;   // col group: cols tcg*6 .. +5
    const int trg = tid >> 5;   // row group: rows trg*8 .. +7
    float acc[8][6];
    #pragma unroll
    for (int i = 0; i < 8; i++)
        #pragma unroll
        for (int j = 0; j < 6; j++) acc[i][j] = 0.0f;

    #pragma unroll 4
    for (int d = 0; d < DHH; d++) {
        float qa[8], kb[6];
        #pragma unroll
        for (int i = 0; i < 8; i++) qa[i] = Qs[d * QTP + trg * 8 + i];
        #pragma unroll
        for (int j = 0; j < 6; j++) kb[j] = Ks[d * KTP + tcg * 6 + j];
        #pragma unroll
        for (int i = 0; i < 8; i++)
            #pragma unroll
            for (int j = 0; j < 6; j++)
                acc[i][j] = fmaf(qa[i], kb[j], acc[i][j]);
    }

    // ---- Add trajectory bias + masks, write to Ps ----
    const float* bias = traj + (size_t)(b * NH + h) * SQ * SQ;
    const float scale = 0.125f;  // 1/sqrt(64)
    #pragma unroll
    for (int i = 0; i < 8; i++) {
        int r = trg * 8 + i;
        int rg = q0 + r;
        #pragma unroll
        for (int j = 0; j < 6; j++) {
            int c = tcg * 6 + j;
            int kg = k0 + c;
            // valid iff kg>=0, kg<=rg (causal), rg-kg<=128 (window)
            float s;
            if (kg >= 0 && c >= r && c <= r + 128)
                s = acc[i][j] * scale + bias[(size_t)rg * SQ + kg];
            else
                s = NEGINF;
            Ps[r * PSP + c] = s;
        }
    }
    __syncthreads();

    // ---- Softmax per row (4 threads / row, 48 cols each) ----
    {
        int row = tid >> 2, sub = tid & 3;
        float* prow = Ps + row * PSP + sub * 48;
        float m = NEGINF;
        #pragma unroll 8
        for (int t = 0; t < 48; t++) m = fmaxf(m, prow[t]);
        m = fmaxf(m, __shfl_xor_sync(0xffffffffu, m, 1));
        m = fmaxf(m, __shfl_xor_sync(0xffffffffu, m, 2));
        float ssum = 0.0f;
        #pragma unroll 8
        for (int t = 0; t < 48; t++) {
            float e = expf(prow[t] - m);
            prow[t] = e;
            ssum += e;
        }
        ssum += __shfl_xor_sync(0xffffffffu, ssum, 1);
        ssum += __shfl_xor_sync(0xffffffffu, ssum, 2);
        float inv = 1.0f / ssum;
        #pragma unroll 8
        for (int t = 0; t < 48; t++) prow[t] *= inv;
    }
    __syncthreads();

    // ---- O = P(64x192) @ V(192x64), microtile 4x4 per thread ----
    {
        int tr2 = tid >> 4;   // 0..15 -> rows tr2*4..+3
        int tc2 = tid & 15;   // 0..15 -> cols tc2*4..+3
        float o[4][4];
        #pragma unroll
        for (int i = 0; i < 4; i++)
            #pragma unroll
            for (int j = 0; j < 4; j++) o[i][j] = 0.0f;

        #pragma unroll 4
        for (int k = 0; k < KT; k++) {
            float p[4], vv[4];
            #pragma unroll
            for (int i = 0; i < 4; i++) p[i] = Ps[(tr2 * 4 + i) * PSP + k];
            #pragma unroll
            for (int j = 0; j < 4; j++) vv[j] = Vs[k * DHP + tc2 * 4 + j];
            #pragma unroll
            for (int i = 0; i < 4; i++)
                #pragma unroll
                for (int j = 0; j < 4; j++)
                    o[i][j] = fmaf(p[i], vv[j], o[i][j]);
        }

        #pragma unroll
        for (int i = 0; i < 4; i++) {
            float* orow = att_out + (size_t)(b * SQ + q0 + tr2 * 4 + i) * DD
                          + h * 64 + tc2 * 4;
            float4 v = make_float4(o[i][0], o[i][1], o[i][2], o[i][3]);
            *(float4*)orow = v;
        }
    }
}

// ============================================================
// Launch
// ============================================================
extern "C" void kernel_launch(void* const* d_in, const int* in_sizes, int n_in,
                              void* d_out, int out_size)
{
    const float* x    = (const float*)d_in[0];
    const float* traj = (const float*)d_in[1];
    // d_in[2] = mask (causal; handled analytically)
    const float* Wqkv = (const float*)d_in[3];
    const float* Wout = (const float*)d_in[4];
    float* out = (float*)d_out;

    void* p;
    cudaGetSymbolAddress(&p, g_qkv);
    float* qkv = (float*)p;
    cudaGetSymbolAddress(&p, g_att);
    float* att = (float*)p;

    // GEMM1: x (4096x1024) @ W_qkv (1024x3072) -> qkv
    {
        dim3 grid(3072 / 128, MTOK / 128);
        sgemm_kernel<<<grid, 256>>>(x, Wqkv, qkv, MTOK, 3072, DD);
    }

    // Banded attention
    {
        cudaFuncSetAttribute(attn_kernel,
                             cudaFuncAttributeMaxDynamicSharedMemorySize,
                             (int)ATTN_SMEM);
        dim3 grid(SQ / QT, NH, BB);
        attn_kernel<<<grid, 256, ATTN_SMEM>>>(traj, att);
    }

    // GEMM2: att (4096x1024) @ W_out (1024x1024) -> out
    {
        dim3 grid(DD / 128, MTOK / 128);
        sgemm_kernel<<<grid, 256>>>(att, Wout, out, MTOK, DD, DD);
    }
}

// round 2
// speedup vs baseline: 1.5718x; 1.5718x over previous
#include <cuda_runtime.h>
#include <cuda_bf16.h>
#include <math.h>
#include <stdint.h>

// Problem constants
#define SQ   2048
#define NH   16
#define DHH  64
#define DD   1024
#define BB   2
#define MTOK 4096   // B*S tokens

// Scratch (device globals — no allocation allowed)
__device__ float g_qkv[(size_t)MTOK * 3072];  // 48 MB
__device__ float g_att[(size_t)MTOK * DD];    // 16 MB
// bf16 split operands
__device__ __nv_bfloat16 g_xh[(size_t)MTOK * DD];
__device__ __nv_bfloat16 g_xl[(size_t)MTOK * DD];
__device__ __nv_bfloat16 g_ah[(size_t)MTOK * DD];
__device__ __nv_bfloat16 g_al[(size_t)MTOK * DD];
__device__ __nv_bfloat16 g_wqh[(size_t)3072 * DD];  // transposed [N][K]
__device__ __nv_bfloat16 g_wql[(size_t)3072 * DD];
__device__ __nv_bfloat16 g_woh[(size_t)DD * DD];
__device__ __nv_bfloat16 g_wol[(size_t)DD * DD];

// ============================================================
// Split fp32 -> bf16 hi/lo (elementwise, vectorized x4)
// ============================================================
__global__ __launch_bounds__(256) void split_kernel(
    const float4* __restrict__ in,
    __nv_bfloat162* __restrict__ hi, __nv_bfloat162* __restrict__ lo, int n4)
{
    int i = blockIdx.x * blockDim.x + threadIdx.x;
    if (i >= n4) return;
    float4 v = in[i];
    __nv_bfloat16 hx = __float2bfloat16(v.x);
    __nv_bfloat16 hy = __float2bfloat16(v.y);
    __nv_bfloat16 hz = __float2bfloat16(v.z);
    __nv_bfloat16 hw = __float2bfloat16(v.w);
    float lx = v.x - __bfloat162float(hx);
    float ly = v.y - __bfloat162float(hy);
    float lz = v.z - __bfloat162float(hz);
    float lw = v.w - __bfloat162float(hw);
    hi[2*i+0] = __nv_bfloat162(hx, hy);
    hi[2*i+1] = __nv_bfloat162(hz, hw);
    lo[2*i+0] = __floats2bfloat162_rn(lx, ly);
    lo[2*i+1] = __floats2bfloat162_rn(lz, lw);
}

// ============================================================
// Transpose + split: B fp32 [K][N] -> Bt hi/lo bf16 [N][K]
// block (32,8), grid (N/32, K/32)
// ============================================================
__global__ __launch_bounds__(256) void tsplit_kernel(
    const float* __restrict__ B,
    __nv_bfloat16* __restrict__ Bht, __nv_bfloat16* __restrict__ Blt,
    int K, int N)
{
    __shared__ float t[32][33];
    int n0 = blockIdx.x * 32, k0 = blockIdx.y * 32;
    for (int j = threadIdx.y; j < 32; j += 8)
        t[j][threadIdx.x] = B[(size_t)(k0 + j) * N + n0 + threadIdx.x];
    __syncthreads();
    for (int j = threadIdx.y; j < 32; j += 8) {
        float v = t[threadIdx.x][j];   // B[k0+tx][n0+j]
        __nv_bfloat16 h = __float2bfloat16(v);
        float r = v - __bfloat162float(h);
        size_t o = (size_t)(n0 + j) * K + k0 + threadIdx.x;
        Bht[o] = h;
        Blt[o] = __float2bfloat16(r);
    }
}

// ============================================================
// bf16x3 split tensor-core GEMM.
// C(MxN fp32) = Ah*Bh + Ah*Bl + Al*Bh  (A row-major [M][K], Bt [N][K])
// 128x128x32 tile, 256 thr, warp tile 64x32, mma.m16n8k16.bf16,
// cp.async double-buffered.
// ============================================================
#define BM 128
#define BN 128
#define BKC 32
#define APITCH 40   // bf16 pitch; 80B row stride (16B-aligned, LDS conflict-free)

__device__ __forceinline__ void mma_bf16(float* c, const uint32_t* a, const uint32_t* b) {
    asm volatile(
        "mma.sync.aligned.m16n8k16.row.col.f32.bf16.bf16.f32 "
        "{%0,%1,%2,%3}, {%4,%5,%6,%7}, {%8,%9}, {%0,%1,%2,%3};"
        : "+f"(c[0]), "+f"(c[1]), "+f"(c[2]), "+f"(c[3])
        : "r"(a[0]), "r"(a[1]), "r"(a[2]), "r"(a[3]), "r"(b[0]), "r"(b[1]));
}

__global__ __launch_bounds__(256) void gemm_bf16x3(
    const __nv_bfloat16* __restrict__ Ah, const __nv_bfloat16* __restrict__ Al,
    const __nv_bfloat16* __restrict__ Bht, const __nv_bfloat16* __restrict__ Blt,
    float* __restrict__ C, int M, int N, int K)
{
    __shared__ __nv_bfloat16 As[2][BM * APITCH];
    __shared__ __nv_bfloat16 Bs[2][BN * APITCH];

    const int tid  = threadIdx.x;
    const int wid  = tid >> 5, lane = tid & 31;
    const int wm   = wid >> 2, wn = wid & 3;     // 2x4 warp grid
    const int g    = lane >> 2, t = lane & 3;

    const int row0 = blockIdx.y * BM;
    const int col0 = blockIdx.x * BN;

    // global->smem load mapping: 2 rows of 8 bf16 per thread per matrix
    const int lr = tid >> 2;        // 0..63
    const int lc = (tid & 3) * 8;   // 0,8,16,24

    const int kchunks = K / BKC;
    const int total   = 3 * kchunks;

    float acc[4][4][4];
    #pragma unroll
    for (int mt = 0; mt < 4; mt++)
        #pragma unroll
        for (int nt = 0; nt < 4; nt++)
            #pragma unroll
            for (int e = 0; e < 4; e++) acc[mt][nt][e] = 0.0f;

    // ---- prefetch helper (segment select + cp.async) ----
    auto prefetch = [&](int c, int buf) {
        int seg = c / kchunks;
        int kk  = (c - seg * kchunks) * BKC;
        const __nv_bfloat16* A  = (seg < 2) ? Ah : Al;
        const __nv_bfloat16* Bt = (seg == 1) ? Blt : Bht;
        #pragma unroll
        for (int rr = 0; rr < 2; rr++) {
            int r = lr + rr * 64;
            uint32_t sa = (uint32_t)__cvta_generic_to_shared(&As[buf][r * APITCH + lc]);
            const void* ga = A + (size_t)(row0 + r) * K + kk + lc;
            asm volatile("cp.async.cg.shared.global [%0], [%1], 16;\n" :: "r"(sa), "l"(ga));
            uint32_t sb = (uint32_t)__cvta_generic_to_shared(&Bs[buf][r * APITCH + lc]);
            const void* gb = Bt + (size_t)(col0 + r) * K + kk + lc;
            asm volatile("cp.async.cg.shared.global [%0], [%1], 16;\n" :: "r"(sb), "l"(gb));
        }
    };

    prefetch(0, 0);
    asm volatile("cp.async.commit_group;\n" ::: "memory");

    for (int c = 0; c < total; c++) {
        int buf = c & 1;
        if (c + 1 < total) {
            prefetch(c + 1, (c + 1) & 1);
            asm volatile("cp.async.commit_group;\n" ::: "memory");
            asm volatile("cp.async.wait_group 1;\n" ::: "memory");
        } else {
            asm volatile("cp.async.wait_group 0;\n" ::: "memory");
        }
        __syncthreads();

        #pragma unroll
        for (int kc = 0; kc < 2; kc++) {
            const int kb = kc * 16;
            uint32_t af[4][4], bf[4][2];
            #pragma unroll
            for (int mt = 0; mt < 4; mt++) {
                const __nv_bfloat16* base =
                    &As[buf][(wm * 64 + mt * 16 + g) * APITCH + kb + 2 * t];
                af[mt][0] = *(const uint32_t*)(base);
                af[mt][1] = *(const uint32_t*)(base + 8 * APITCH);
                af[mt][2] = *(const uint32_t*)(base + 8);
                af[mt][3] = *(const uint32_t*)(base + 8 * APITCH + 8);
            }
            #pragma unroll
            for (int nt = 0; nt < 4; nt++) {
                const __nv_bfloat16* base =
                    &Bs[buf][(wn * 32 + nt * 8 + g) * APITCH + kb + 2 * t];
                bf[nt][0] = *(const uint32_t*)(base);
                bf[nt][1] = *(const uint32_t*)(base + 8);
            }
            #pragma unroll
            for (int mt = 0; mt < 4; mt++)
                #pragma unroll
                for (int nt = 0; nt < 4; nt++)
                    mma_bf16(acc[mt][nt], af[mt], bf[nt]);
        }
        __syncthreads();
    }

    // ---- epilogue ----
    #pragma unroll
    for (int mt = 0; mt < 4; mt++) {
        #pragma unroll
        for (int nt = 0; nt < 4; nt++) {
            int r  = row0 + wm * 64 + mt * 16 + g;
            int cc = col0 + wn * 32 + nt * 8 + 2 * t;
            float2 v0 = make_float2(acc[mt][nt][0], acc[mt][nt][1]);
            float2 v1 = make_float2(acc[mt][nt][2], acc[mt][nt][3]);
            *(float2*)&C[(size_t)r * N + cc]       = v0;
            *(float2*)&C[(size_t)(r + 8) * N + cc] = v1;
        }
    }
}

// ============================================================
// Banded attention (unchanged from R1): causal ∧ |i-j|<=128.
// ============================================================
#define QT   64
#define KT   192
#define QTP  65
#define KTP  193
#define DHP  65
#define PSP  196
#define ATTN_SMEM ((DHH*QTP + DHH*KTP + KT*DHP + QT*PSP) * sizeof(float))

__global__ __launch_bounds__(256) void attn_kernel(
    const float* __restrict__ traj, float* __restrict__ att_out)
{
    extern __shared__ float sm[];
    float* Qs = sm;
    float* Ks = Qs + DHH * QTP;
    float* Vs = Ks + DHH * KTP;
    float* Ps = Vs + KT * DHP;

    const int tid = threadIdx.x;
    const int b = blockIdx.z, h = blockIdx.y;
    const int q0 = blockIdx.x * QT;
    const int k0 = q0 - 128;
    const float NEGINF = __int_as_float(0xff800000);

    const float* qkbase = g_qkv + (size_t)b * SQ * 3072;

    for (int idx = tid; idx < QT * DHH; idx += 256) {
        int d = idx & 63, r = idx >> 6;
        Qs[d * QTP + r] = qkbase[(size_t)(q0 + r) * 3072 + h * 64 + d];
    }
    for (int idx = tid; idx < KT * DHH; idx += 256) {
        int d = idx & 63, kk = idx >> 6;
        int key = k0 + kk;
        float kv = 0.0f, vv = 0.0f;
        if (key >= 0) {
            const float* p = qkbase + (size_t)key * 3072 + 1024 + h * 64 + d;
            kv = p[0];
            vv = p[1024];
        }
        Ks[d * KTP + kk] = kv;
        Vs[kk * DHP + d] = vv;
    }
    __syncthreads();

    const int tcg = tid & 31;
    const int trg = tid >> 5;
    float acc[8][6];
    #pragma unroll
    for (int i = 0; i < 8; i++)
        #pragma unroll
        for (int j = 0; j < 6; j++) acc[i][j] = 0.0f;

    #pragma unroll 4
    for (int d = 0; d < DHH; d++) {
        float qa[8], kb[6];
        #pragma unroll
        for (int i = 0; i < 8; i++) qa[i] = Qs[d * QTP + trg * 8 + i];
        #pragma unroll
        for (int j = 0; j < 6; j++) kb[j] = Ks[d * KTP + tcg * 6 + j];
        #pragma unroll
        for (int i = 0; i < 8; i++)
            #pragma unroll
            for (int j = 0; j < 6; j++)
                acc[i][j] = fmaf(qa[i], kb[j], acc[i][j]);
    }

    const float* bias = traj + (size_t)(b * NH + h) * SQ * SQ;
    const float scale = 0.125f;
    #pragma unroll
    for (int i = 0; i < 8; i++) {
        int r = trg * 8 + i;
        int rg = q0 + r;
        #pragma unroll
        for (int j = 0; j < 6; j++) {
            int c = tcg * 6 + j;
            int kg = k0 + c;
            float s;
            if (kg >= 0 && c >= r && c <= r + 128)
                s = acc[i][j] * scale + bias[(size_t)rg * SQ + kg];
            else
                s = NEGINF;
            Ps[r * PSP + c] = s;
        }
    }
    __syncthreads();

    {
        int row = tid >> 2, sub = tid & 3;
        float* prow = Ps + row * PSP + sub * 48;
        float m = NEGINF;
        #pragma unroll 8
        for (int t = 0; t < 48; t++) m = fmaxf(m, prow[t]);
        m = fmaxf(m, __shfl_xor_sync(0xffffffffu, m, 1));
        m = fmaxf(m, __shfl_xor_sync(0xffffffffu, m, 2));
        float ssum = 0.0f;
        #pragma unroll 8
        for (int t = 0; t < 48; t++) {
            float e = expf(prow[t] - m);
            prow[t] = e;
            ssum += e;
        }
        ssum += __shfl_xor_sync(0xffffffffu, ssum, 1);
        ssum += __shfl_xor_sync(0xffffffffu, ssum, 2);
        float inv = 1.0f / ssum;
        #pragma unroll 8
        for (int t = 0; t < 48; t++) prow[t] *= inv;
    }
    __syncthreads();

    {
        int tr2 = tid >> 4;
        int tc2 = tid & 15;
        float o[4][4];
        #pragma unroll
        for (int i = 0; i < 4; i++)
            #pragma unroll
            for (int j = 0; j < 4; j++) o[i][j] = 0.0f;

        #pragma unroll 4
        for (int k = 0; k < KT; k++) {
            float p[4], vv[4];
            #pragma unroll
            for (int i = 0; i < 4; i++) p[i] = Ps[(tr2 * 4 + i) * PSP + k];
            #pragma unroll
            for (int j = 0; j < 4; j++) vv[j] = Vs[k * DHP + tc2 * 4 + j];
            #pragma unroll
            for (int i = 0; i < 4; i++)
                #pragma unroll
                for (int j = 0; j < 4; j++)
                    o[i][j] = fmaf(p[i], vv[j], o[i][j]);
        }

        #pragma unroll
        for (int i = 0; i < 4; i++) {
            float* orow = g_att + (size_t)(b * SQ + q0 + tr2 * 4 + i) * DD
                          + h * 64 + tc2 * 4;
            float4 v = make_float4(o[i][0], o[i][1], o[i][2], o[i][3]);
            *(float4*)orow = v;
        }
    }
}

// ============================================================
// Launch
// ============================================================
extern "C" void kernel_launch(void* const* d_in, const int* in_sizes, int n_in,
                              void* d_out, int out_size)
{
    const float* x    = (const float*)d_in[0];
    const float* traj = (const float*)d_in[1];
    // d_in[2] = mask (handled analytically)
    const float* Wqkv = (const float*)d_in[3];
    const float* Wout = (const float*)d_in[4];
    float* out = (float*)d_out;

    void* p;
    cudaGetSymbolAddress(&p, g_qkv);  float* qkv = (float*)p;
    cudaGetSymbolAddress(&p, g_att);  float* att = (float*)p;
    cudaGetSymbolAddress(&p, g_xh);   __nv_bfloat16* xh = (__nv_bfloat16*)p;
    cudaGetSymbolAddress(&p, g_xl);   __nv_bfloat16* xl = (__nv_bfloat16*)p;
    cudaGetSymbolAddress(&p, g_ah);   __nv_bfloat16* ah = (__nv_bfloat16*)p;
    cudaGetSymbolAddress(&p, g_al);   __nv_bfloat16* al = (__nv_bfloat16*)p;
    cudaGetSymbolAddress(&p, g_wqh);  __nv_bfloat16* wqh = (__nv_bfloat16*)p;
    cudaGetSymbolAddress(&p, g_wql);  __nv_bfloat16* wql = (__nv_bfloat16*)p;
    cudaGetSymbolAddress(&p, g_woh);  __nv_bfloat16* woh = (__nv_bfloat16*)p;
    cudaGetSymbolAddress(&p, g_wol);  __nv_bfloat16* wol = (__nv_bfloat16*)p;

    // 1. split x into bf16 hi/lo
    {
        int n4 = MTOK * DD / 4;
        split_kernel<<<(n4 + 255) / 256, 256>>>(
            (const float4*)x, (__nv_bfloat162*)xh, (__nv_bfloat162*)xl, n4);
    }
    // 2. transpose+split weights
    {
        dim3 grid(3072 / 32, DD / 32);
        tsplit_kernel<<<grid, dim3(32, 8)>>>(Wqkv, wqh, wql, DD, 3072);
    }
    {
        dim3 grid(DD / 32, DD / 32);
        tsplit_kernel<<<grid, dim3(32, 8)>>>(Wout, woh, wol, DD, DD);
    }
    // 3. GEMM1: qkv = x @ W_qkv  (4096x3072, K=1024)
    {
        dim3 grid(3072 / BN, MTOK / BM);
        gemm_bf16x3<<<grid, 256>>>(xh, xl, wqh, wql, qkv, MTOK, 3072, DD);
    }
    // 4. banded attention
    {
        cudaFuncSetAttribute(attn_kernel,
                             cudaFuncAttributeMaxDynamicSharedMemorySize,
                             (int)ATTN_SMEM);
        dim3 grid(SQ / QT, NH, BB);
        attn_kernel<<<grid, 256, ATTN_SMEM>>>(traj, nullptr);
    }
    // 5. split attention output
    {
        int n4 = MTOK * DD / 4;
        split_kernel<<<(n4 + 255) / 256, 256>>>(
            (const float4*)att, (__nv_bfloat162*)ah, (__nv_bfloat162*)al, n4);
    }
    // 6. GEMM2: out = att @ W_out  (4096x1024, K=1024)
    {
        dim3 grid(DD / BN, MTOK / BM);
        gemm_bf16x3<<<grid, 256>>>(ah, al, woh, wol, out, MTOK, DD, DD);
    }
}

// round 3
// speedup vs baseline: 2.0921x; 1.3310x over previous
#include <cuda_runtime.h>
#include <cuda_bf16.h>
#include <cuda_fp16.h>
#include <math.h>
#include <stdint.h>

#define SQ   2048
#define NH   16
#define DD   1024
#define BB   2
#define MTOK 4096

// Scratch
__device__ float g_qkv[(size_t)MTOK * 3072];
__device__ __nv_bfloat16 g_xh[(size_t)MTOK * DD];
__device__ __nv_bfloat16 g_xl[(size_t)MTOK * DD];
__device__ __nv_bfloat16 g_ah[(size_t)MTOK * DD];
__device__ __nv_bfloat16 g_al[(size_t)MTOK * DD];
__device__ __nv_bfloat16 g_wqh[(size_t)3072 * DD];
__device__ __nv_bfloat16 g_wql[(size_t)3072 * DD];
__device__ __nv_bfloat16 g_woh[(size_t)DD * DD];
__device__ __nv_bfloat16 g_wol[(size_t)DD * DD];

// ---------------- helpers ----------------
__device__ __forceinline__ void ldsm4(uint32_t* r, uint32_t addr) {
    asm volatile("ldmatrix.sync.aligned.m8n8.x4.shared.b16 {%0,%1,%2,%3}, [%4];"
        : "=r"(r[0]), "=r"(r[1]), "=r"(r[2]), "=r"(r[3]) : "r"(addr));
}
__device__ __forceinline__ void mma_bf16(float* c, const uint32_t* a, const uint32_t* b) {
    asm volatile(
        "mma.sync.aligned.m16n8k16.row.col.f32.bf16.bf16.f32 "
        "{%0,%1,%2,%3}, {%4,%5,%6,%7}, {%8,%9}, {%0,%1,%2,%3};"
        : "+f"(c[0]), "+f"(c[1]), "+f"(c[2]), "+f"(c[3])
        : "r"(a[0]), "r"(a[1]), "r"(a[2]), "r"(a[3]), "r"(b[0]), "r"(b[1]));
}
__device__ __forceinline__ void mma_f16(float* c, const uint32_t* a, const uint32_t* b) {
    asm volatile(
        "mma.sync.aligned.m16n8k16.row.col.f32.f16.f16.f32 "
        "{%0,%1,%2,%3}, {%4,%5,%6,%7}, {%8,%9}, {%0,%1,%2,%3};"
        : "+f"(c[0]), "+f"(c[1]), "+f"(c[2]), "+f"(c[3])
        : "r"(a[0]), "r"(a[1]), "r"(a[2]), "r"(a[3]), "r"(b[0]), "r"(b[1]));
}
__device__ __forceinline__ void cpasync16(uint32_t dst, const void* src) {
    asm volatile("cp.async.cg.shared.global [%0], [%1], 16;\n" :: "r"(dst), "l"(src));
}

// ---------------- split kernels ----------------
__global__ __launch_bounds__(256) void split_kernel(
    const float4* __restrict__ in,
    __nv_bfloat162* __restrict__ hi, __nv_bfloat162* __restrict__ lo, int n4)
{
    int i = blockIdx.x * blockDim.x + threadIdx.x;
    if (i >= n4) return;
    float4 v = in[i];
    __nv_bfloat16 hx = __float2bfloat16(v.x);
    __nv_bfloat16 hy = __float2bfloat16(v.y);
    __nv_bfloat16 hz = __float2bfloat16(v.z);
    __nv_bfloat16 hw = __float2bfloat16(v.w);
    hi[2*i+0] = __nv_bfloat162(hx, hy);
    hi[2*i+1] = __nv_bfloat162(hz, hw);
    lo[2*i+0] = __floats2bfloat162_rn(v.x - __bfloat162float(hx), v.y - __bfloat162float(hy));
    lo[2*i+1] = __floats2bfloat162_rn(v.z - __bfloat162float(hz), v.w - __bfloat162float(hw));
}

__global__ __launch_bounds__(256) void tsplit_kernel(
    const float* __restrict__ B,
    __nv_bfloat16* __restrict__ Bht, __nv_bfloat16* __restrict__ Blt,
    int K, int N)
{
    __shared__ float t[32][33];
    int n0 = blockIdx.x * 32, k0 = blockIdx.y * 32;
    for (int j = threadIdx.y; j < 32; j += 8)
        t[j][threadIdx.x] = B[(size_t)(k0 + j) * N + n0 + threadIdx.x];
    __syncthreads();
    for (int j = threadIdx.y; j < 32; j += 8) {
        float v = t[threadIdx.x][j];
        __nv_bfloat16 h = __float2bfloat16(v);
        size_t o = (size_t)(n0 + j) * K + k0 + threadIdx.x;
        Bht[o] = h;
        Blt[o] = __float2bfloat16(v - __bfloat162float(h));
    }
}

// ============================================================
// bf16x3 GEMM, BK=64, ldmatrix, 2-stage cp.async
// ============================================================
#define GP    72        // smem pitch (bf16): 64 + 8
#define GMAT  9216      // halves per matrix per stage (128*72)
#define GSTG  18432     // halves per stage

__global__ __launch_bounds__(256, 2) void gemm_bf16x3(
    const __nv_bfloat16* __restrict__ Ah, const __nv_bfloat16* __restrict__ Al,
    const __nv_bfloat16* __restrict__ Bht, const __nv_bfloat16* __restrict__ Blt,
    float* __restrict__ C, int M, int N, int K)
{
    extern __shared__ __nv_bfloat16 sm[];

    const int tid  = threadIdx.x;
    const int lane = tid & 31, wid = tid >> 5;
    const int wm   = wid >> 2, wn = wid & 3;
    const int g    = lane >> 2, t = lane & 3;

    const int row0 = blockIdx.y * 128;
    const int col0 = blockIdx.x * 128;

    const int kchunks = K / 64;
    const int total   = 3 * kchunks;

    // ldmatrix per-lane offsets
    const int aRow = lane & 15;
    const int aK   = (lane & 16) ? 8 : 0;
    const int bRow = (lane & 7) + ((lane & 16) ? 8 : 0);
    const int bK   = lane & 8;

    float acc[4][4][4];
    #pragma unroll
    for (int mt = 0; mt < 4; mt++)
        #pragma unroll
        for (int nt = 0; nt < 4; nt++)
            #pragma unroll
            for (int e = 0; e < 4; e++) acc[mt][nt][e] = 0.0f;

    auto prefetch = [&](int c, int s) {
        int seg = c / kchunks;
        int kk  = (c - seg * kchunks) * 64;
        const __nv_bfloat16* A  = (seg < 2) ? Ah : Al;
        const __nv_bfloat16* Bt = (seg == 1) ? Blt : Bht;
        __nv_bfloat16* as = sm + s * GSTG;
        __nv_bfloat16* bs = as + GMAT;
        #pragma unroll
        for (int p = 0; p < 4; p++) {
            int ch  = tid + p * 256;
            int row = ch >> 3;
            int col = (ch & 7) * 8;
            cpasync16((uint32_t)__cvta_generic_to_shared(&as[row * GP + col]),
                      A + (size_t)(row0 + row) * K + kk + col);
            cpasync16((uint32_t)__cvta_generic_to_shared(&bs[row * GP + col]),
                      Bt + (size_t)(col0 + row) * K + kk + col);
        }
    };

    prefetch(0, 0);
    asm volatile("cp.async.commit_group;\n" ::: "memory");

    for (int c = 0; c < total; c++) {
        int buf = c & 1;
        if (c + 1 < total) {
            prefetch(c + 1, buf ^ 1);
            asm volatile("cp.async.commit_group;\n" ::: "memory");
            asm volatile("cp.async.wait_group 1;\n" ::: "memory");
        } else {
            asm volatile("cp.async.wait_group 0;\n" ::: "memory");
        }
        __syncthreads();

        uint32_t sa = (uint32_t)__cvta_generic_to_shared(sm + buf * GSTG);
        uint32_t sb = (uint32_t)__cvta_generic_to_shared(sm + buf * GSTG + GMAT);

        #pragma unroll
        for (int ks = 0; ks < 4; ks++) {
            const int kb = ks * 16;
            uint32_t af[4][4], bfr[2][4];
            #pragma unroll
            for (int mt = 0; mt < 4; mt++)
                ldsm4(af[mt], sa + 2u * ((wm * 64 + mt * 16 + aRow) * GP + kb + aK));
            #pragma unroll
            for (int p = 0; p < 2; p++)
                ldsm4(bfr[p], sb + 2u * ((wn * 32 + p * 16 + bRow) * GP + kb + bK));
            #pragma unroll
            for (int mt = 0; mt < 4; mt++)
                #pragma unroll
                for (int nt = 0; nt < 4; nt++)
                    mma_bf16(acc[mt][nt], af[mt], &bfr[nt >> 1][(nt & 1) * 2]);
        }
        __syncthreads();
    }

    #pragma unroll
    for (int mt = 0; mt < 4; mt++) {
        #pragma unroll
        for (int nt = 0; nt < 4; nt++) {
            int r  = row0 + wm * 64 + mt * 16 + g;
            int cc = col0 + wn * 32 + nt * 8 + 2 * t;
            *(float2*)&C[(size_t)r * N + cc]       = make_float2(acc[mt][nt][0], acc[mt][nt][1]);
            *(float2*)&C[(size_t)(r + 8) * N + cc] = make_float2(acc[mt][nt][2], acc[mt][nt][3]);
        }
    }
}

// ============================================================
// Banded attention with fp16 split tensor-core mma.
// Per block: (b, h, 64 q-rows) x 192-key window [q0-128, q0+63].
// S = QhKh + QhKl + QlKh ; O = PhVh + PhVl + PlVh
// ============================================================
#define QP   72     // Q/K smem pitch (half)
#define VP   200    // Vt / Ph pitch (half)
#define PSP  196    // Ps pitch (float)

// smem byte offsets
#define OF_QH  0
#define OF_QL  9216
#define OF_KH  18432
#define OF_KL  46080
#define OF_VH  73728
#define OF_VL  99328
#define OF_PS  124928
#define OF_PH  0        // overlay (Q/K dead after scores)
#define OF_PL  25600
#define ATTN_SMEM (124928 + 64*PSP*4)   // 175104

__global__ __launch_bounds__(256) void attn_kernel(const float* __restrict__ traj)
{
    extern __shared__ char asmem[];
    half*  Qh = (half*)(asmem + OF_QH);
    half*  Ql = (half*)(asmem + OF_QL);
    half*  Kh = (half*)(asmem + OF_KH);
    half*  Kl = (half*)(asmem + OF_KL);
    half*  Vh = (half*)(asmem + OF_VH);
    half*  Vl = (half*)(asmem + OF_VL);
    float* Ps = (float*)(asmem + OF_PS);
    half*  Ph = (half*)(asmem + OF_PH);
    half*  Pl = (half*)(asmem + OF_PL);

    const int tid  = threadIdx.x;
    const int lane = tid & 31, wid = tid >> 5;
    const int wm   = wid >> 2, wn = wid & 3;
    const int g    = lane >> 2, t = lane & 3;
    const int b = blockIdx.z, h = blockIdx.y;
    const int q0 = blockIdx.x * 64;
    const int k0 = q0 - 128;
    const float NEGINF = __int_as_float(0xff800000);

    const int aRow = lane & 15;
    const int aK   = (lane & 16) ? 8 : 0;
    const int bRow = (lane & 7) + ((lane & 16) ? 8 : 0);
    const int bK   = lane & 8;

    const float* qkbase = g_qkv + (size_t)b * SQ * 3072;

    // ---- load Q (split) ----
    for (int idx = tid; idx < 64 * 64; idx += 256) {
        int r = idx >> 6, d = idx & 63;
        float v = qkbase[(size_t)(q0 + r) * 3072 + h * 64 + d];
        half hh = __float2half(v);
        Qh[r * QP + d] = hh;
        Ql[r * QP + d] = __float2half(v - __half2float(hh));
    }
    // ---- load K, V (split; V transposed) ----
    for (int idx = tid; idx < 192 * 64; idx += 256) {
        int kk = idx >> 6, d = idx & 63;
        int key = k0 + kk;
        float kv = 0.0f, vv = 0.0f;
        if (key >= 0) {
            const float* p = qkbase + (size_t)key * 3072 + 1024 + h * 64 + d;
            kv = p[0];
            vv = p[1024];
        }
        half kh = __float2half(kv);
        Kh[kk * QP + d] = kh;
        Kl[kk * QP + d] = __float2half(kv - __half2float(kh));
        half vh = __float2half(vv);
        Vh[d * VP + kk] = vh;
        Vl[d * VP + kk] = __float2half(vv - __half2float(vh));
    }
    __syncthreads();

    // ---- scores: 3-pass fp16 mma, warp tile 32x48 ----
    float acc[2][6][4];
    #pragma unroll
    for (int mt = 0; mt < 2; mt++)
        #pragma unroll
        for (int nt = 0; nt < 6; nt++)
            #pragma unroll
            for (int e = 0; e < 4; e++) acc[mt][nt][e] = 0.0f;

    #pragma unroll
    for (int seg = 0; seg < 3; seg++) {
        uint32_t aq = (uint32_t)__cvta_generic_to_shared(seg == 2 ? Ql : Qh);
        uint32_t bk = (uint32_t)__cvta_generic_to_shared(seg == 1 ? Kl : Kh);
        #pragma unroll
        for (int ks = 0; ks < 4; ks++) {
            const int kb = ks * 16;
            uint32_t af[2][4], bfr[3][4];
            #pragma unroll
            for (int mt = 0; mt < 2; mt++)
                ldsm4(af[mt], aq + 2u * ((wm * 32 + mt * 16 + aRow) * QP + kb + aK));
            #pragma unroll
            for (int p = 0; p < 3; p++)
                ldsm4(bfr[p], bk + 2u * ((wn * 48 + p * 16 + bRow) * QP + kb + bK));
            #pragma unroll
            for (int mt = 0; mt < 2; mt++)
                #pragma unroll
                for (int nt = 0; nt < 6; nt++)
                    mma_f16(acc[mt][nt], af[mt], &bfr[nt >> 1][(nt & 1) * 2]);
        }
    }

    // ---- scale + bias + mask -> Ps ----
    {
        const float* bias = traj + (size_t)(b * NH + h) * SQ * SQ;
        #pragma unroll
        for (int mt = 0; mt < 2; mt++) {
            #pragma unroll
            for (int nt = 0; nt < 6; nt++) {
                int rl = wm * 32 + mt * 16 + g;
                int cl = wn * 48 + nt * 8 + 2 * t;
                #pragma unroll
                for (int e = 0; e < 4; e++) {
                    int row = rl + ((e & 2) ? 8 : 0);
                    int col = cl + (e & 1);
                    int kg = k0 + col;
                    float s;
                    if (kg >= 0 && col >= row && col <= row + 128)
                        s = acc[mt][nt][e] * 0.125f + bias[(size_t)(q0 + row) * SQ + kg];
                    else
                        s = NEGINF;
                    Ps[row * PSP + col] = s;
                }
            }
        }
    }
    __syncthreads();

    // ---- softmax (4 threads/row), write Ph/Pl (overlay) ----
    {
        int row = tid >> 2, sub = tid & 3;
        float* prow = Ps + row * PSP + sub * 48;
        float m = NEGINF;
        #pragma unroll 8
        for (int i = 0; i < 48; i++) m = fmaxf(m, prow[i]);
        m = fmaxf(m, __shfl_xor_sync(0xffffffffu, m, 1));
        m = fmaxf(m, __shfl_xor_sync(0xffffffffu, m, 2));
        float ssum = 0.0f;
        float ebuf[48];
        #pragma unroll 8
        for (int i = 0; i < 48; i++) {
            float e = expf(prow[i] - m);
            ebuf[i] = e;
            ssum += e;
        }
        ssum += __shfl_xor_sync(0xffffffffu, ssum, 1);
        ssum += __shfl_xor_sync(0xffffffffu, ssum, 2);
        float inv = 1.0f / ssum;
        half* phrow = Ph + row * VP + sub * 48;
        half* plrow = Pl + row * VP + sub * 48;
        #pragma unroll 8
        for (int i = 0; i < 48; i++) {
            float pv = ebuf[i] * inv;
            half hh = __float2half(pv);
            phrow[i] = hh;
            plrow[i] = __float2half(pv - __half2float(hh));
        }
    }
    __syncthreads();

    // ---- O = PV: 3-pass fp16 mma, warp tile 32x16, k=192 ----
    float o[2][2][4];
    #pragma unroll
    for (int mt = 0; mt < 2; mt++)
        #pragma unroll
        for (int nt = 0; nt < 2; nt++)
            #pragma unroll
            for (int e = 0; e < 4; e++) o[mt][nt][e] = 0.0f;

    #pragma unroll
    for (int seg = 0; seg < 3; seg++) {
        uint32_t ap = (uint32_t)__cvta_generic_to_shared(seg == 2 ? Pl : Ph);
        uint32_t bv = (uint32_t)__cvta_generic_to_shared(seg == 1 ? Vl : Vh);
        for (int ks = 0; ks < 12; ks++) {
            const int kb = ks * 16;
            uint32_t af[2][4], bfr[4];
            #pragma unroll
            for (int mt = 0; mt < 2; mt++)
                ldsm4(af[mt], ap + 2u * ((wm * 32 + mt * 16 + aRow) * VP + kb + aK));
            ldsm4(bfr, bv + 2u * ((wn * 16 + bRow) * VP + kb + bK));
            #pragma unroll
            for (int mt = 0; mt < 2; mt++)
                #pragma unroll
                for (int nt = 0; nt < 2; nt++)
                    mma_f16(o[mt][nt], af[mt], &bfr[nt * 2]);
        }
    }

    // ---- epilogue: write bf16 hi/lo directly ----
    #pragma unroll
    for (int mt = 0; mt < 2; mt++) {
        #pragma unroll
        for (int nt = 0; nt < 2; nt++) {
            int rl = wm * 32 + mt * 16 + g;
            int d  = wn * 16 + nt * 8 + 2 * t;
            #pragma unroll
            for (int half_i = 0; half_i < 2; half_i++) {
                int row = rl + half_i * 8;
                float v0 = o[mt][nt][half_i * 2 + 0];
                float v1 = o[mt][nt][half_i * 2 + 1];
                __nv_bfloat16 h0 = __float2bfloat16(v0);
                __nv_bfloat16 h1 = __float2bfloat16(v1);
                size_t off = (size_t)(b * SQ + q0 + row) * DD + h * 64 + d;
                *(__nv_bfloat162*)(g_ah + off) = __nv_bfloat162(h0, h1);
                *(__nv_bfloat162*)(g_al + off) = __floats2bfloat162_rn(
                    v0 - __bfloat162float(h0), v1 - __bfloat162float(h1));
            }
        }
    }
}

// ============================================================
// Launch
// ============================================================
extern "C" void kernel_launch(void* const* d_in, const int* in_sizes, int n_in,
                              void* d_out, int out_size)
{
    const float* x    = (const float*)d_in[0];
    const float* traj = (const float*)d_in[1];
    const float* Wqkv = (const float*)d_in[3];
    const float* Wout = (const float*)d_in[4];
    float* out = (float*)d_out;

    void* p;
    cudaGetSymbolAddress(&p, g_qkv);  float* qkv = (float*)p;
    cudaGetSymbolAddress(&p, g_xh);   __nv_bfloat16* xh = (__nv_bfloat16*)p;
    cudaGetSymbolAddress(&p, g_xl);   __nv_bfloat16* xl = (__nv_bfloat16*)p;
    cudaGetSymbolAddress(&p, g_ah);   __nv_bfloat16* ah = (__nv_bfloat16*)p;
    cudaGetSymbolAddress(&p, g_al);   __nv_bfloat16* al = (__nv_bfloat16*)p;
    cudaGetSymbolAddress(&p, g_wqh);  __nv_bfloat16* wqh = (__nv_bfloat16*)p;
    cudaGetSymbolAddress(&p, g_wql);  __nv_bfloat16* wql = (__nv_bfloat16*)p;
    cudaGetSymbolAddress(&p, g_woh);  __nv_bfloat16* woh = (__nv_bfloat16*)p;
    cudaGetSymbolAddress(&p, g_wol);  __nv_bfloat16* wol = (__nv_bfloat16*)p;

    const int GEMM_SMEM = 2 * GSTG * (int)sizeof(__nv_bfloat16);  // 73728

    // split x
    {
        int n4 = MTOK * DD / 4;
        split_kernel<<<(n4 + 255) / 256, 256>>>(
            (const float4*)x, (__nv_bfloat162*)xh, (__nv_bfloat162*)xl, n4);
    }
    // transpose+split weights
    {
        dim3 grid(3072 / 32, DD / 32);
        tsplit_kernel<<<grid, dim3(32, 8)>>>(Wqkv, wqh, wql, DD, 3072);
    }
    {
        dim3 grid(DD / 32, DD / 32);
        tsplit_kernel<<<grid, dim3(32, 8)>>>(Wout, woh, wol, DD, DD);
    }
    // GEMM1
    {
        cudaFuncSetAttribute(gemm_bf16x3,
            cudaFuncAttributeMaxDynamicSharedMemorySize, GEMM_SMEM);
        dim3 grid(3072 / 128, MTOK / 128);
        gemm_bf16x3<<<grid, 256, GEMM_SMEM>>>(xh, xl, wqh, wql, qkv, MTOK, 3072, DD);
    }
    // attention
    {
        cudaFuncSetAttribute(attn_kernel,
            cudaFuncAttributeMaxDynamicSharedMemorySize, ATTN_SMEM);
        dim3 grid(SQ / 64, NH, BB);
        attn_kernel<<<grid, 256, ATTN_SMEM>>>(traj);
    }
    // GEMM2
    {
        dim3 grid(DD / 128, MTOK / 128);
        gemm_bf16x3<<<grid, 256, GEMM_SMEM>>>(ah, al, woh, wol, out, MTOK, DD, DD);
    }
}

// round 5
// speedup vs baseline: 2.3531x; 1.1248x over previous
#include <cuda_runtime.h>
#include <cuda_bf16.h>
#include <cuda_fp16.h>
#include <math.h>
#include <stdint.h>

#define SQ   2048
#define NH   16
#define DD   1024
#define BB   2
#define MTOK 4096

// Scratch
__device__ float g_qkv[(size_t)MTOK * 3072];
__device__ __nv_bfloat16 g_xh[(size_t)MTOK * DD];
__device__ __nv_bfloat16 g_xl[(size_t)MTOK * DD];
__device__ __nv_bfloat16 g_ah[(size_t)MTOK * DD];
__device__ __nv_bfloat16 g_al[(size_t)MTOK * DD];
__device__ __nv_bfloat16 g_wqh[(size_t)3072 * DD];
__device__ __nv_bfloat16 g_wql[(size_t)3072 * DD];
__device__ __nv_bfloat16 g_woh[(size_t)DD * DD];
__device__ __nv_bfloat16 g_wol[(size_t)DD * DD];

// ---------------- helpers ----------------
__device__ __forceinline__ uint32_t smem_u32(const void* p) {
    uint32_t a;
    asm("{ .reg .u64 t; cvta.to.shared.u64 t, %1; cvt.u32.u64 %0, t; }" : "=r"(a) : "l"(p));
    return a;
}
__device__ __forceinline__ void cpasync16(uint32_t dst, const void* src) {
    asm volatile("cp.async.cg.shared.global [%0], [%1], 16;\n" :: "r"(dst), "l"(src));
}
#define CP_COMMIT() asm volatile("cp.async.commit_group;\n" ::: "memory")
#define SWZ128(o) ((o) ^ (((o) >> 3) & 0x70))

__device__ __forceinline__ void ldsm4(uint32_t* r, uint32_t addr) {
    asm volatile("ldmatrix.sync.aligned.m8n8.x4.shared.b16 {%0,%1,%2,%3}, [%4];"
        : "=r"(r[0]), "=r"(r[1]), "=r"(r[2]), "=r"(r[3]) : "r"(addr));
}
__device__ __forceinline__ void mma_bf16(float* c, const uint32_t* a, const uint32_t* b) {
    asm volatile(
        "mma.sync.aligned.m16n8k16.row.col.f32.bf16.bf16.f32 "
        "{%0,%1,%2,%3}, {%4,%5,%6,%7}, {%8,%9}, {%0,%1,%2,%3};"
        : "+f"(c[0]), "+f"(c[1]), "+f"(c[2]), "+f"(c[3])
        : "r"(a[0]), "r"(a[1]), "r"(a[2]), "r"(a[3]), "r"(b[0]), "r"(b[1]));
}
__device__ __forceinline__ void mma_f16(float* c, const uint32_t* a, const uint32_t* b) {
    asm volatile(
        "mma.sync.aligned.m16n8k16.row.col.f32.f16.f16.f32 "
        "{%0,%1,%2,%3}, {%4,%5,%6,%7}, {%8,%9}, {%0,%1,%2,%3};"
        : "+f"(c[0]), "+f"(c[1]), "+f"(c[2]), "+f"(c[3])
        : "r"(a[0]), "r"(a[1]), "r"(a[2]), "r"(a[3]), "r"(b[0]), "r"(b[1]));
}

// ---------------- split kernels ----------------
__global__ __launch_bounds__(256) void split_kernel(
    const float4* __restrict__ in,
    __nv_bfloat162* __restrict__ hi, __nv_bfloat162* __restrict__ lo, int n4)
{
    int i = blockIdx.x * blockDim.x + threadIdx.x;
    if (i >= n4) return;
    float4 v = in[i];
    __nv_bfloat16 hx = __float2bfloat16(v.x);
    __nv_bfloat16 hy = __float2bfloat16(v.y);
    __nv_bfloat16 hz = __float2bfloat16(v.z);
    __nv_bfloat16 hw = __float2bfloat16(v.w);
    hi[2*i+0] = __nv_bfloat162(hx, hy);
    hi[2*i+1] = __nv_bfloat162(hz, hw);
    lo[2*i+0] = __floats2bfloat162_rn(v.x - __bfloat162float(hx), v.y - __bfloat162float(hy));
    lo[2*i+1] = __floats2bfloat162_rn(v.z - __bfloat162float(hz), v.w - __bfloat162float(hw));
}

__global__ __launch_bounds__(256) void tsplit_kernel(
    const float* __restrict__ B,
    __nv_bfloat16* __restrict__ Bht, __nv_bfloat16* __restrict__ Blt,
    int K, int N)
{
    __shared__ float t[32][33];
    int n0 = blockIdx.x * 32, k0 = blockIdx.y * 32;
    for (int j = threadIdx.y; j < 32; j += 8)
        t[j][threadIdx.x] = B[(size_t)(k0 + j) * N + n0 + threadIdx.x];
    __syncthreads();
    for (int j = threadIdx.y; j < 32; j += 8) {
        float v = t[threadIdx.x][j];
        __nv_bfloat16 h = __float2bfloat16(v);
        size_t o = (size_t)(n0 + j) * K + k0 + threadIdx.x;
        Bht[o] = h;
        Blt[o] = __float2bfloat16(v - __bfloat162float(h));
    }
}

// ============================================================
// bf16x3 fused GEMM (mma.sync). Tile 128x128, BK=64.
// Per k-chunk: load Ah/Al/Bh/Bl tiles once; per k-step issue
// AhBh + AhBl + AlBh into ONE accumulator (48 HMMA / ks).
// 3-stage cp.async pipeline, SW128 swizzled smem (conflict-free),
// single __syncthreads per chunk, register-double-buffered frags.
// ============================================================
#define GT_AH  0
#define GT_AL  16384
#define GT_BH  32768
#define GT_BL  49152
#define GSTGB  65536
#define GEMM_SMEM (3 * GSTGB + 1024)

__global__ __launch_bounds__(256) void gemm_bf16x3(
    const __nv_bfloat16* __restrict__ Ah, const __nv_bfloat16* __restrict__ Al,
    const __nv_bfloat16* __restrict__ Bh, const __nv_bfloat16* __restrict__ Bl,
    float* __restrict__ C, int M, int N, int K)
{
    extern __shared__ char gsm[];
    const uint32_t sbase = (smem_u32(gsm) + 1023u) & ~1023u;

    const int tid  = threadIdx.x;
    const int lane = tid & 31, wid = tid >> 5;
    const int wm   = wid >> 2, wn = wid & 3;     // 2x4 warps, warp tile 64x32
    const int g    = lane >> 2, t = lane & 3;
    const int row0 = blockIdx.y * 128;
    const int col0 = blockIdx.x * 128;
    const int nch  = K >> 6;

    const int aRow = lane & 15;
    const int aK   = (lane & 16) ? 8 : 0;
    const int bRow = (lane & 7) + ((lane & 16) ? 8 : 0);
    const int bK   = lane & 8;

    float acc[4][4][4];
    #pragma unroll
    for (int mt = 0; mt < 4; mt++)
        #pragma unroll
        for (int nt = 0; nt < 4; nt++)
            #pragma unroll
            for (int e = 0; e < 4; e++) acc[mt][nt][e] = 0.0f;

    auto load_chunk = [&](int c, int s) {
        const uint32_t base = sbase + (uint32_t)s * GSTGB;
        const int kk = c * 64;
        #pragma unroll
        for (int i = 0; i < 4; i++) {
            int u = tid + i * 256;              // 0..1023
            int r = u >> 3, sg = u & 7;
            uint32_t so = SWZ128((uint32_t)(r * 128 + sg * 16));
            size_t goA = (size_t)(row0 + r) * K + kk + sg * 8;
            size_t goB = (size_t)(col0 + r) * K + kk + sg * 8;
            cpasync16(base + GT_AH + so, Ah + goA);
            cpasync16(base + GT_AL + so, Al + goA);
            cpasync16(base + GT_BH + so, Bh + goB);
            cpasync16(base + GT_BL + so, Bl + goB);
        }
    };

    load_chunk(0, 0); CP_COMMIT();
    if (nch > 1) { load_chunk(1, 1); CP_COMMIT(); }

    // fragment double buffers
    uint32_t afh[2][4][4], afl[2][4][4], bfh[2][2][4], bfl[2][2][4];

    int buf = 0;
    for (int c = 0; c < nch; c++) {
        if (c < nch - 1) asm volatile("cp.async.wait_group 1;\n" ::: "memory");
        else             asm volatile("cp.async.wait_group 0;\n" ::: "memory");
        __syncthreads();

        if (c + 2 < nch) {
            int s = buf - 1; if (s < 0) s += 3;   // (c+2)%3
            load_chunk(c + 2, s);
            CP_COMMIT();
        }

        const uint32_t bAH = sbase + (uint32_t)buf * GSTGB + GT_AH;
        const uint32_t bAL = bAH + (GT_AL - GT_AH);
        const uint32_t bBH = bAH + (GT_BH - GT_AH);
        const uint32_t bBL = bAH + (GT_BL - GT_AH);

        // load frags for ks=0
        {
            const int kb = 0;
            #pragma unroll
            for (int mt = 0; mt < 4; mt++) {
                uint32_t so = SWZ128((uint32_t)((wm*64 + mt*16 + aRow) * 128 + (kb + aK) * 2));
                ldsm4(afh[0][mt], bAH + so);
                ldsm4(afl[0][mt], bAL + so);
            }
            #pragma unroll
            for (int p = 0; p < 2; p++) {
                uint32_t so = SWZ128((uint32_t)((wn*32 + p*16 + bRow) * 128 + (kb + bK) * 2));
                ldsm4(bfh[0][p], bBH + so);
                ldsm4(bfl[0][p], bBL + so);
            }
        }

        #pragma unroll
        for (int ks = 0; ks < 4; ks++) {
            const int cur = ks & 1, nxt = cur ^ 1;
            if (ks < 3) {
                const int kb = (ks + 1) * 16;
                #pragma unroll
                for (int mt = 0; mt < 4; mt++) {
                    uint32_t so = SWZ128((uint32_t)((wm*64 + mt*16 + aRow) * 128 + (kb + aK) * 2));
                    ldsm4(afh[nxt][mt], bAH + so);
                    ldsm4(afl[nxt][mt], bAL + so);
                }
                #pragma unroll
                for (int p = 0; p < 2; p++) {
                    uint32_t so = SWZ128((uint32_t)((wn*32 + p*16 + bRow) * 128 + (kb + bK) * 2));
                    ldsm4(bfh[nxt][p], bBH + so);
                    ldsm4(bfl[nxt][p], bBL + so);
                }
            }
            #pragma unroll
            for (int mt = 0; mt < 4; mt++) {
                #pragma unroll
                for (int nt = 0; nt < 4; nt++) {
                    const uint32_t* bh = &bfh[cur][nt >> 1][(nt & 1) * 2];
                    const uint32_t* bl = &bfl[cur][nt >> 1][(nt & 1) * 2];
                    mma_bf16(acc[mt][nt], afh[cur][mt], bh);
                    mma_bf16(acc[mt][nt], afh[cur][mt], bl);
                    mma_bf16(acc[mt][nt], afl[cur][mt], bh);
                }
            }
        }

        if (++buf == 3) buf = 0;
    }

    #pragma unroll
    for (int mt = 0; mt < 4; mt++) {
        #pragma unroll
        for (int nt = 0; nt < 4; nt++) {
            int r  = row0 + wm * 64 + mt * 16 + g;
            int cc = col0 + wn * 32 + nt * 8 + 2 * t;
            *(float2*)&C[(size_t)r * N + cc]       = make_float2(acc[mt][nt][0], acc[mt][nt][1]);
            *(float2*)&C[(size_t)(r + 8) * N + cc] = make_float2(acc[mt][nt][2], acc[mt][nt][3]);
        }
    }
}

// ============================================================
// Banded attention with fp16 split tensor-core mma (R3, proven).
// ============================================================
#define QP   72
#define VP   200
#define PSP  196
#define OF_QH  0
#define OF_QL  9216
#define OF_KH  18432
#define OF_KL  46080
#define OF_VH  73728
#define OF_VL  99328
#define OF_PS  124928
#define OF_PH  0
#define OF_PL  25600
#define ATTN_SMEM (124928 + 64*PSP*4)

__global__ __launch_bounds__(256) void attn_kernel(const float* __restrict__ traj)
{
    extern __shared__ char asmem[];
    half*  Qh = (half*)(asmem + OF_QH);
    half*  Ql = (half*)(asmem + OF_QL);
    half*  Kh = (half*)(asmem + OF_KH);
    half*  Kl = (half*)(asmem + OF_KL);
    half*  Vh = (half*)(asmem + OF_VH);
    half*  Vl = (half*)(asmem + OF_VL);
    float* Ps = (float*)(asmem + OF_PS);
    half*  Ph = (half*)(asmem + OF_PH);
    half*  Pl = (half*)(asmem + OF_PL);

    const int tid  = threadIdx.x;
    const int lane = tid & 31, wid = tid >> 5;
    const int wm   = wid >> 2, wn = wid & 3;
    const int g    = lane >> 2, t = lane & 3;
    const int b = blockIdx.z, h = blockIdx.y;
    const int q0 = blockIdx.x * 64;
    const int k0 = q0 - 128;
    const float NEGINF = __int_as_float(0xff800000);

    const int aRow = lane & 15;
    const int aK   = (lane & 16) ? 8 : 0;
    const int bRow = (lane & 7) + ((lane & 16) ? 8 : 0);
    const int bK   = lane & 8;

    const float* qkbase = g_qkv + (size_t)b * SQ * 3072;

    for (int idx = tid; idx < 64 * 64; idx += 256) {
        int r = idx >> 6, d = idx & 63;
        float v = qkbase[(size_t)(q0 + r) * 3072 + h * 64 + d];
        half hh = __float2half(v);
        Qh[r * QP + d] = hh;
        Ql[r * QP + d] = __float2half(v - __half2float(hh));
    }
    for (int idx = tid; idx < 192 * 64; idx += 256) {
        int kk = idx >> 6, d = idx & 63;
        int key = k0 + kk;
        float kv = 0.0f, vv = 0.0f;
        if (key >= 0) {
            const float* p = qkbase + (size_t)key * 3072 + 1024 + h * 64 + d;
            kv = p[0];
            vv = p[1024];
        }
        half kh = __float2half(kv);
        Kh[kk * QP + d] = kh;
        Kl[kk * QP + d] = __float2half(kv - __half2float(kh));
        half vh = __float2half(vv);
        Vh[d * VP + kk] = vh;
        Vl[d * VP + kk] = __float2half(vv - __half2float(vh));
    }
    __syncthreads();

    float acc[2][6][4];
    #pragma unroll
    for (int mt = 0; mt < 2; mt++)
        #pragma unroll
        for (int nt = 0; nt < 6; nt++)
            #pragma unroll
            for (int e = 0; e < 4; e++) acc[mt][nt][e] = 0.0f;

    #pragma unroll
    for (int seg = 0; seg < 3; seg++) {
        uint32_t aq = smem_u32(seg == 2 ? Ql : Qh);
        uint32_t bk = smem_u32(seg == 1 ? Kl : Kh);
        #pragma unroll
        for (int ks = 0; ks < 4; ks++) {
            const int kb = ks * 16;
            uint32_t af[2][4], bfr[3][4];
            #pragma unroll
            for (int mt = 0; mt < 2; mt++)
                ldsm4(af[mt], aq + 2u * ((wm * 32 + mt * 16 + aRow) * QP + kb + aK));
            #pragma unroll
            for (int p = 0; p < 3; p++)
                ldsm4(bfr[p], bk + 2u * ((wn * 48 + p * 16 + bRow) * QP + kb + bK));
            #pragma unroll
            for (int mt = 0; mt < 2; mt++)
                #pragma unroll
                for (int nt = 0; nt < 6; nt++)
                    mma_f16(acc[mt][nt], af[mt], &bfr[nt >> 1][(nt & 1) * 2]);
        }
    }

    {
        const float* bias = traj + (size_t)(b * NH + h) * SQ * SQ;
        #pragma unroll
        for (int mt = 0; mt < 2; mt++) {
            #pragma unroll
            for (int nt = 0; nt < 6; nt++) {
                int rl = wm * 32 + mt * 16 + g;
                int cl = wn * 48 + nt * 8 + 2 * t;
                #pragma unroll
                for (int e = 0; e < 4; e++) {
                    int row = rl + ((e & 2) ? 8 : 0);
                    int col = cl + (e & 1);
                    int kg = k0 + col;
                    float s;
                    if (kg >= 0 && col >= row && col <= row + 128)
                        s = acc[mt][nt][e] * 0.125f + bias[(size_t)(q0 + row) * SQ + kg];
                    else
                        s = NEGINF;
                    Ps[row * PSP + col] = s;
                }
            }
        }
    }
    __syncthreads();

    {
        int row = tid >> 2, sub = tid & 3;
        float* prow = Ps + row * PSP + sub * 48;
        float m = NEGINF;
        #pragma unroll 8
        for (int i = 0; i < 48; i++) m = fmaxf(m, prow[i]);
        m = fmaxf(m, __shfl_xor_sync(0xffffffffu, m, 1));
        m = fmaxf(m, __shfl_xor_sync(0xffffffffu, m, 2));
        float ssum = 0.0f;
        float ebuf[48];
        #pragma unroll 8
        for (int i = 0; i < 48; i++) {
            float e = expf(prow[i] - m);
            ebuf[i] = e;
            ssum += e;
        }
        ssum += __shfl_xor_sync(0xffffffffu, ssum, 1);
        ssum += __shfl_xor_sync(0xffffffffu, ssum, 2);
        float inv = 1.0f / ssum;
        half* phrow = Ph + row * VP + sub * 48;
        half* plrow = Pl + row * VP + sub * 48;
        #pragma unroll 8
        for (int i = 0; i < 48; i++) {
            float pv = ebuf[i] * inv;
            half hh = __float2half(pv);
            phrow[i] = hh;
            plrow[i] = __float2half(pv - __half2float(hh));
        }
    }
    __syncthreads();

    float o[2][2][4];
    #pragma unroll
    for (int mt = 0; mt < 2; mt++)
        #pragma unroll
        for (int nt = 0; nt < 2; nt++)
            #pragma unroll
            for (int e = 0; e < 4; e++) o[mt][nt][e] = 0.0f;

    #pragma unroll
    for (int seg = 0; seg < 3; seg++) {
        uint32_t ap = smem_u32(seg == 2 ? Pl : Ph);
        uint32_t bv = smem_u32(seg == 1 ? Vl : Vh);
        for (int ks = 0; ks < 12; ks++) {
            const int kb = ks * 16;
            uint32_t af[2][4], bfr[4];
            #pragma unroll
            for (int mt = 0; mt < 2; mt++)
                ldsm4(af[mt], ap + 2u * ((wm * 32 + mt * 16 + aRow) * VP + kb + aK));
            ldsm4(bfr, bv + 2u * ((wn * 16 + bRow) * VP + kb + bK));
            #pragma unroll
            for (int mt = 0; mt < 2; mt++)
                #pragma unroll
                for (int nt = 0; nt < 2; nt++)
                    mma_f16(o[mt][nt], af[mt], &bfr[nt * 2]);
        }
    }

    #pragma unroll
    for (int mt = 0; mt < 2; mt++) {
        #pragma unroll
        for (int nt = 0; nt < 2; nt++) {
            int rl = wm * 32 + mt * 16 + g;
            int d  = wn * 16 + nt * 8 + 2 * t;
            #pragma unroll
            for (int half_i = 0; half_i < 2; half_i++) {
                int row = rl + half_i * 8;
                float v0 = o[mt][nt][half_i * 2 + 0];
                float v1 = o[mt][nt][half_i * 2 + 1];
                __nv_bfloat16 h0 = __float2bfloat16(v0);
                __nv_bfloat16 h1 = __float2bfloat16(v1);
                size_t off = (size_t)(b * SQ + q0 + row) * DD + h * 64 + d;
                *(__nv_bfloat162*)(g_ah + off) = __nv_bfloat162(h0, h1);
                *(__nv_bfloat162*)(g_al + off) = __floats2bfloat162_rn(
                    v0 - __bfloat162float(h0), v1 - __bfloat162float(h1));
            }
        }
    }
}

// ============================================================
// Launch
// ============================================================
extern "C" void kernel_launch(void* const* d_in, const int* in_sizes, int n_in,
                              void* d_out, int out_size)
{
    const float* x    = (const float*)d_in[0];
    const float* traj = (const float*)d_in[1];
    const float* Wqkv = (const float*)d_in[3];
    const float* Wout = (const float*)d_in[4];
    float* out = (float*)d_out;

    void* p;
    cudaGetSymbolAddress(&p, g_qkv);  float* qkv = (float*)p;
    cudaGetSymbolAddress(&p, g_xh);   __nv_bfloat16* xh = (__nv_bfloat16*)p;
    cudaGetSymbolAddress(&p, g_xl);   __nv_bfloat16* xl = (__nv_bfloat16*)p;
    cudaGetSymbolAddress(&p, g_ah);   __nv_bfloat16* ah = (__nv_bfloat16*)p;
    cudaGetSymbolAddress(&p, g_al);   __nv_bfloat16* al = (__nv_bfloat16*)p;
    cudaGetSymbolAddress(&p, g_wqh);  __nv_bfloat16* wqh = (__nv_bfloat16*)p;
    cudaGetSymbolAddress(&p, g_wql);  __nv_bfloat16* wql = (__nv_bfloat16*)p;
    cudaGetSymbolAddress(&p, g_woh);  __nv_bfloat16* woh = (__nv_bfloat16*)p;
    cudaGetSymbolAddress(&p, g_wol);  __nv_bfloat16* wol = (__nv_bfloat16*)p;

    // split x
    {
        int n4 = MTOK * DD / 4;
        split_kernel<<<(n4 + 255) / 256, 256>>>(
            (const float4*)x, (__nv_bfloat162*)xh, (__nv_bfloat162*)xl, n4);
    }
    // transpose+split weights
    {
        dim3 grid(3072 / 32, DD / 32);
        tsplit_kernel<<<grid, dim3(32, 8)>>>(Wqkv, wqh, wql, DD, 3072);
    }
    {
        dim3 grid(DD / 32, DD / 32);
        tsplit_kernel<<<grid, dim3(32, 8)>>>(Wout, woh, wol, DD, DD);
    }
    // GEMM1: qkv = x @ W_qkv
    {
        cudaFuncSetAttribute(gemm_bf16x3,
            cudaFuncAttributeMaxDynamicSharedMemorySize, GEMM_SMEM);
        dim3 grid(3072 / 128, MTOK / 128);
        gemm_bf16x3<<<grid, 256, GEMM_SMEM>>>(xh, xl, wqh, wql, qkv, MTOK, 3072, DD);
    }
    // attention
    {
        cudaFuncSetAttribute(attn_kernel,
            cudaFuncAttributeMaxDynamicSharedMemorySize, ATTN_SMEM);
        dim3 grid(SQ / 64, NH, BB);
        attn_kernel<<<grid, 256, ATTN_SMEM>>>(traj);
    }
    // GEMM2: out = att @ W_out
    {
        dim3 grid(DD / 128, MTOK / 128);
        gemm_bf16x3<<<grid, 256, GEMM_SMEM>>>(ah, al, woh, wol, out, MTOK, DD, DD);
    }
}

// round 8
// speedup vs baseline: 2.4312x; 1.0332x over previous
#include <cuda_runtime.h>
#include <cuda_bf16.h>
#include <cuda_fp16.h>
#include <math.h>
#include <stdint.h>

#define SQ   2048
#define NH   16
#define DD   1024
#define BB   2
#define MTOK 4096

// Scratch
__device__ float g_qkv[(size_t)MTOK * 3072];
__device__ __nv_bfloat16 g_xh[(size_t)MTOK * DD];
__device__ __nv_bfloat16 g_xl[(size_t)MTOK * DD];
__device__ __nv_bfloat16 g_ah[(size_t)MTOK * DD];
__device__ __nv_bfloat16 g_al[(size_t)MTOK * DD];
__device__ __nv_bfloat16 g_wqh[(size_t)3072 * DD];
__device__ __nv_bfloat16 g_wql[(size_t)3072 * DD];
__device__ __nv_bfloat16 g_woh[(size_t)DD * DD];
__device__ __nv_bfloat16 g_wol[(size_t)DD * DD];

// ---------------- helpers ----------------
__device__ __forceinline__ uint32_t smem_u32(const void* p) {
    uint32_t a;
    asm("{ .reg .u64 t; cvta.to.shared.u64 t, %1; cvt.u32.u64 %0, t; }" : "=r"(a) : "l"(p));
    return a;
}
__device__ __forceinline__ void cpasync16(uint32_t dst, const void* src) {
    asm volatile("cp.async.cg.shared.global [%0], [%1], 16;\n" :: "r"(dst), "l"(src));
}
#define CP_COMMIT() asm volatile("cp.async.commit_group;\n" ::: "memory")
#define SWZ128(o) ((o) ^ (((o) >> 3) & 0x70))

__device__ __forceinline__ void ldsm4(uint32_t* r, uint32_t addr) {
    asm volatile("ldmatrix.sync.aligned.m8n8.x4.shared.b16 {%0,%1,%2,%3}, [%4];"
        : "=r"(r[0]), "=r"(r[1]), "=r"(r[2]), "=r"(r[3]) : "r"(addr));
}
__device__ __forceinline__ void mma_bf16(float* c, const uint32_t* a, const uint32_t* b) {
    asm volatile(
        "mma.sync.aligned.m16n8k16.row.col.f32.bf16.bf16.f32 "
        "{%0,%1,%2,%3}, {%4,%5,%6,%7}, {%8,%9}, {%0,%1,%2,%3};"
        : "+f"(c[0]), "+f"(c[1]), "+f"(c[2]), "+f"(c[3])
        : "r"(a[0]), "r"(a[1]), "r"(a[2]), "r"(a[3]), "r"(b[0]), "r"(b[1]));
}
__device__ __forceinline__ void mma_f16(float* c, const uint32_t* a, const uint32_t* b) {
    asm volatile(
        "mma.sync.aligned.m16n8k16.row.col.f32.f16.f16.f32 "
        "{%0,%1,%2,%3}, {%4,%5,%6,%7}, {%8,%9}, {%0,%1,%2,%3};"
        : "+f"(c[0]), "+f"(c[1]), "+f"(c[2]), "+f"(c[3])
        : "r"(a[0]), "r"(a[1]), "r"(a[2]), "r"(a[3]), "r"(b[0]), "r"(b[1]));
}

// ---------------- split kernels ----------------
__global__ __launch_bounds__(256) void split_kernel(
    const float4* __restrict__ in,
    __nv_bfloat162* __restrict__ hi, __nv_bfloat162* __restrict__ lo, int n4)
{
    int i = blockIdx.x * blockDim.x + threadIdx.x;
    if (i >= n4) return;
    float4 v = in[i];
    __nv_bfloat16 hx = __float2bfloat16(v.x);
    __nv_bfloat16 hy = __float2bfloat16(v.y);
    __nv_bfloat16 hz = __float2bfloat16(v.z);
    __nv_bfloat16 hw = __float2bfloat16(v.w);
    hi[2*i+0] = __nv_bfloat162(hx, hy);
    hi[2*i+1] = __nv_bfloat162(hz, hw);
    lo[2*i+0] = __floats2bfloat162_rn(v.x - __bfloat162float(hx), v.y - __bfloat162float(hy));
    lo[2*i+1] = __floats2bfloat162_rn(v.z - __bfloat162float(hz), v.w - __bfloat162float(hw));
}

__global__ __launch_bounds__(256) void tsplit_kernel(
    const float* __restrict__ B,
    __nv_bfloat16* __restrict__ Bht, __nv_bfloat16* __restrict__ Blt,
    int K, int N)
{
    __shared__ float t[32][33];
    int n0 = blockIdx.x * 32, k0 = blockIdx.y * 32;
    for (int j = threadIdx.y; j < 32; j += 8)
        t[j][threadIdx.x] = B[(size_t)(k0 + j) * N + n0 + threadIdx.x];
    __syncthreads();
    for (int j = threadIdx.y; j < 32; j += 8) {
        float v = t[threadIdx.x][j];
        __nv_bfloat16 h = __float2bfloat16(v);
        size_t o = (size_t)(n0 + j) * K + k0 + threadIdx.x;
        Bht[o] = h;
        Blt[o] = __float2bfloat16(v - __bfloat162float(h));
    }
}

// ============================================================
// bf16x3 fused GEMM (mma.sync). Tile 128x128, BK=64, 512 threads,
// 4x4 warp grid, warp tile 32x32. 3-stage cp.async pipeline,
// SW128 swizzled smem, one __syncthreads per chunk.
// ============================================================
#define GT_AH  0
#define GT_AL  16384
#define GT_BH  32768
#define GT_BL  49152
#define GSTGB  65536
#define GEMM_SMEM (3 * GSTGB + 1024)

__global__ __launch_bounds__(512) void gemm_bf16x3(
    const __nv_bfloat16* __restrict__ Ah, const __nv_bfloat16* __restrict__ Al,
    const __nv_bfloat16* __restrict__ Bh, const __nv_bfloat16* __restrict__ Bl,
    float* __restrict__ C, int M, int N, int K)
{
    extern __shared__ char gsm[];
    const uint32_t sbase = (smem_u32(gsm) + 1023u) & ~1023u;

    const int tid  = threadIdx.x;
    const int lane = tid & 31, wid = tid >> 5;
    const int wm   = wid >> 2, wn = wid & 3;     // 4x4 warps, warp tile 32x32
    const int g    = lane >> 2, t = lane & 3;
    const int row0 = blockIdx.y * 128;
    const int col0 = blockIdx.x * 128;
    const int nch  = K >> 6;

    const int aRow = lane & 15;
    const int aK   = (lane & 16) ? 8 : 0;
    const int bRow = (lane & 7) + ((lane & 16) ? 8 : 0);
    const int bK   = lane & 8;

    float acc[2][4][4];
    #pragma unroll
    for (int mt = 0; mt < 2; mt++)
        #pragma unroll
        for (int nt = 0; nt < 4; nt++)
            #pragma unroll
            for (int e = 0; e < 4; e++) acc[mt][nt][e] = 0.0f;

    auto load_chunk = [&](int c, int s) {
        const uint32_t base = sbase + (uint32_t)s * GSTGB;
        const int kk = c * 64;
        #pragma unroll
        for (int i = 0; i < 2; i++) {
            int u = tid + i * 512;              // 0..1023
            int r = u >> 3, sg = u & 7;
            uint32_t so = SWZ128((uint32_t)(r * 128 + sg * 16));
            size_t goA = (size_t)(row0 + r) * K + kk + sg * 8;
            size_t goB = (size_t)(col0 + r) * K + kk + sg * 8;
            cpasync16(base + GT_AH + so, Ah + goA);
            cpasync16(base + GT_AL + so, Al + goA);
            cpasync16(base + GT_BH + so, Bh + goB);
            cpasync16(base + GT_BL + so, Bl + goB);
        }
    };

    load_chunk(0, 0); CP_COMMIT();
    if (nch > 1) { load_chunk(1, 1); CP_COMMIT(); }

    int buf = 0;
    for (int c = 0; c < nch; c++) {
        if (c < nch - 1) asm volatile("cp.async.wait_group 1;\n" ::: "memory");
        else             asm volatile("cp.async.wait_group 0;\n" ::: "memory");
        __syncthreads();

        if (c + 2 < nch) {
            int s = buf - 1; if (s < 0) s += 3;   // (c+2)%3
            load_chunk(c + 2, s);
            CP_COMMIT();
        }

        const uint32_t bAH = sbase + (uint32_t)buf * GSTGB + GT_AH;
        const uint32_t bAL = bAH + (GT_AL - GT_AH);
        const uint32_t bBH = bAH + (GT_BH - GT_AH);
        const uint32_t bBL = bAH + (GT_BL - GT_AH);

        #pragma unroll
        for (int ks = 0; ks < 4; ks++) {
            const int kb = ks * 16;
            uint32_t afh[2][4], afl[2][4], bfh[2][4], bfl[2][4];
            #pragma unroll
            for (int mt = 0; mt < 2; mt++) {
                uint32_t so = SWZ128((uint32_t)((wm*32 + mt*16 + aRow) * 128 + (kb + aK) * 2));
                ldsm4(afh[mt], bAH + so);
                ldsm4(afl[mt], bAL + so);
            }
            #pragma unroll
            for (int p = 0; p < 2; p++) {
                uint32_t so = SWZ128((uint32_t)((wn*32 + p*16 + bRow) * 128 + (kb + bK) * 2));
                ldsm4(bfh[p], bBH + so);
                ldsm4(bfl[p], bBL + so);
            }
            #pragma unroll
            for (int mt = 0; mt < 2; mt++) {
                #pragma unroll
                for (int nt = 0; nt < 4; nt++) {
                    const uint32_t* bh = &bfh[nt >> 1][(nt & 1) * 2];
                    const uint32_t* bl = &bfl[nt >> 1][(nt & 1) * 2];
                    mma_bf16(acc[mt][nt], afh[mt], bh);
                    mma_bf16(acc[mt][nt], afh[mt], bl);
                    mma_bf16(acc[mt][nt], afl[mt], bh);
                }
            }
        }

        if (++buf == 3) buf = 0;
    }

    #pragma unroll
    for (int mt = 0; mt < 2; mt++) {
        #pragma unroll
        for (int nt = 0; nt < 4; nt++) {
            int r  = row0 + wm * 32 + mt * 16 + g;
            int cc = col0 + wn * 32 + nt * 8 + 2 * t;
            *(float2*)&C[(size_t)r * N + cc]       = make_float2(acc[mt][nt][0], acc[mt][nt][1]);
            *(float2*)&C[(size_t)(r + 8) * N + cc] = make_float2(acc[mt][nt][2], acc[mt][nt][3]);
        }
    }
}

// ============================================================
// Banded attention, fp16 split mma + cp.async bias prefetch.
// ============================================================
#define QP   72
#define VP   200
#define PSP  196
#define OF_QH  0
#define OF_QL  9216
#define OF_KH  18432
#define OF_KL  46080
#define OF_VH  73728
#define OF_VL  99328
#define OF_PS  124928
#define OF_PH  0
#define OF_PL  25600
#define ATTN_SMEM (124928 + 64*PSP*4)

__global__ __launch_bounds__(256) void attn_kernel(const float* __restrict__ traj)
{
    extern __shared__ char asmem[];
    half*  Qh = (half*)(asmem + OF_QH);
    half*  Ql = (half*)(asmem + OF_QL);
    half*  Kh = (half*)(asmem + OF_KH);
    half*  Kl = (half*)(asmem + OF_KL);
    half*  Vh = (half*)(asmem + OF_VH);
    half*  Vl = (half*)(asmem + OF_VL);
    float* Ps = (float*)(asmem + OF_PS);
    half*  Ph = (half*)(asmem + OF_PH);
    half*  Pl = (half*)(asmem + OF_PL);

    const int tid  = threadIdx.x;
    const int lane = tid & 31, wid = tid >> 5;
    const int wm   = wid >> 2, wn = wid & 3;
    const int g    = lane >> 2, t = lane & 3;
    const int b = blockIdx.z, h = blockIdx.y;
    const int q0 = blockIdx.x * 64;
    const int k0 = q0 - 128;
    const float NEGINF = __int_as_float(0xff800000);

    const int aRow = lane & 15;
    const int aK   = (lane & 16) ? 8 : 0;
    const int bRow = (lane & 7) + ((lane & 16) ? 8 : 0);
    const int bK   = lane & 8;

    const float* qkbase = g_qkv + (size_t)b * SQ * 3072;
    const float* bias = traj + (size_t)(b * NH + h) * SQ * SQ;

    // ---- prefetch bias band (64 rows x 192 cols) into Ps via cp.async ----
    {
        const uint32_t psb = smem_u32(Ps);
        #pragma unroll
        for (int i = 0; i < 12; i++) {
            int u = tid + i * 256;            // 0..3071
            int row = u / 48;                 // q row 0..63
            int c4  = u % 48;                 // 16B chunk
            int kg  = k0 + c4 * 4;
            if (kg >= 0) {
                cpasync16(psb + (uint32_t)(row * PSP + c4 * 4) * 4,
                          bias + (size_t)(q0 + row) * SQ + kg);
            }
        }
        CP_COMMIT();
    }

    // ---- load Q/K/V with hi/lo split ----
    for (int idx = tid; idx < 64 * 64; idx += 256) {
        int r = idx >> 6, d = idx & 63;
        float v = qkbase[(size_t)(q0 + r) * 3072 + h * 64 + d];
        half hh = __float2half(v);
        Qh[r * QP + d] = hh;
        Ql[r * QP + d] = __float2half(v - __half2float(hh));
    }
    for (int idx = tid; idx < 192 * 64; idx += 256) {
        int kk = idx >> 6, d = idx & 63;
        int key = k0 + kk;
        float kv = 0.0f, vv = 0.0f;
        if (key >= 0) {
            const float* p = qkbase + (size_t)key * 3072 + 1024 + h * 64 + d;
            kv = p[0];
            vv = p[1024];
        }
        half kh = __float2half(kv);
        Kh[kk * QP + d] = kh;
        Kl[kk * QP + d] = __float2half(kv - __half2float(kh));
        half vh = __float2half(vv);
        Vh[d * VP + kk] = vh;
        Vl[d * VP + kk] = __float2half(vv - __half2float(vh));
    }
    __syncthreads();

    // ---- scores: 3-pass fp16 mma, warp tile 32x48 ----
    float acc[2][6][4];
    #pragma unroll
    for (int mt = 0; mt < 2; mt++)
        #pragma unroll
        for (int nt = 0; nt < 6; nt++)
            #pragma unroll
            for (int e = 0; e < 4; e++) acc[mt][nt][e] = 0.0f;

    #pragma unroll
    for (int seg = 0; seg < 3; seg++) {
        uint32_t aq = smem_u32(seg == 2 ? Ql : Qh);
        uint32_t bk = smem_u32(seg == 1 ? Kl : Kh);
        #pragma unroll
        for (int ks = 0; ks < 4; ks++) {
            const int kb = ks * 16;
            uint32_t af[2][4], bfr[3][4];
            #pragma unroll
            for (int mt = 0; mt < 2; mt++)
                ldsm4(af[mt], aq + 2u * ((wm * 32 + mt * 16 + aRow) * QP + kb + aK));
            #pragma unroll
            for (int p = 0; p < 3; p++)
                ldsm4(bfr[p], bk + 2u * ((wn * 48 + p * 16 + bRow) * QP + kb + bK));
            #pragma unroll
            for (int mt = 0; mt < 2; mt++)
                #pragma unroll
                for (int nt = 0; nt < 6; nt++)
                    mma_f16(acc[mt][nt], af[mt], &bfr[nt >> 1][(nt & 1) * 2]);
        }
    }

    // bias must be resident + visible to all threads
    asm volatile("cp.async.wait_group 0;\n" ::: "memory");
    __syncthreads();

    // ---- scale + bias(smem) + mask -> Ps ----
    {
        #pragma unroll
        for (int mt = 0; mt < 2; mt++) {
            #pragma unroll
            for (int nt = 0; nt < 6; nt++) {
                int rl = wm * 32 + mt * 16 + g;
                int cl = wn * 48 + nt * 8 + 2 * t;
                #pragma unroll
                for (int e = 0; e < 4; e++) {
                    int row = rl + ((e & 2) ? 8 : 0);
                    int col = cl + (e & 1);
                    int kg = k0 + col;
                    float s;
                    if (kg >= 0 && col >= row && col <= row + 128)
                        s = acc[mt][nt][e] * 0.125f + Ps[row * PSP + col];
                    else
                        s = NEGINF;
                    Ps[row * PSP + col] = s;
                }
            }
        }
    }
    __syncthreads();

    // ---- softmax, write Ph/Pl ----
    {
        int row = tid >> 2, sub = tid & 3;
        float* prow = Ps + row * PSP + sub * 48;
        float m = NEGINF;
        #pragma unroll 8
        for (int i = 0; i < 48; i++) m = fmaxf(m, prow[i]);
        m = fmaxf(m, __shfl_xor_sync(0xffffffffu, m, 1));
        m = fmaxf(m, __shfl_xor_sync(0xffffffffu, m, 2));
        float ssum = 0.0f;
        float ebuf[48];
        #pragma unroll 8
        for (int i = 0; i < 48; i++) {
            float e = expf(prow[i] - m);
            ebuf[i] = e;
            ssum += e;
        }
        ssum += __shfl_xor_sync(0xffffffffu, ssum, 1);
        ssum += __shfl_xor_sync(0xffffffffu, ssum, 2);
        float inv = 1.0f / ssum;
        half* phrow = Ph + row * VP + sub * 48;
        half* plrow = Pl + row * VP + sub * 48;
        #pragma unroll 8
        for (int i = 0; i < 48; i++) {
            float pv = ebuf[i] * inv;
            half hh = __float2half(pv);
            phrow[i] = hh;
            plrow[i] = __float2half(pv - __half2float(hh));
        }
    }
    __syncthreads();

    // ---- O = PV: 3-pass fp16 mma ----
    float o[2][2][4];
    #pragma unroll
    for (int mt = 0; mt < 2; mt++)
        #pragma unroll
        for (int nt = 0; nt < 2; nt++)
            #pragma unroll
            for (int e = 0; e < 4; e++) o[mt][nt][e] = 0.0f;

    #pragma unroll
    for (int seg = 0; seg < 3; seg++) {
        uint32_t ap = smem_u32(seg == 2 ? Pl : Ph);
        uint32_t bv = smem_u32(seg == 1 ? Vl : Vh);
        for (int ks = 0; ks < 12; ks++) {
            const int kb = ks * 16;
            uint32_t af[2][4], bfr[4];
            #pragma unroll
            for (int mt = 0; mt < 2; mt++)
                ldsm4(af[mt], ap + 2u * ((wm * 32 + mt * 16 + aRow) * VP + kb + aK));
            ldsm4(bfr, bv + 2u * ((wn * 16 + bRow) * VP + kb + bK));
            #pragma unroll
            for (int mt = 0; mt < 2; mt++)
                #pragma unroll
                for (int nt = 0; nt < 2; nt++)
                    mma_f16(o[mt][nt], af[mt], &bfr[nt * 2]);
        }
    }

    #pragma unroll
    for (int mt = 0; mt < 2; mt++) {
        #pragma unroll
        for (int nt = 0; nt < 2; nt++) {
            int rl = wm * 32 + mt * 16 + g;
            int d  = wn * 16 + nt * 8 + 2 * t;
            #pragma unroll
            for (int half_i = 0; half_i < 2; half_i++) {
                int row = rl + half_i * 8;
                float v0 = o[mt][nt][half_i * 2 + 0];
                float v1 = o[mt][nt][half_i * 2 + 1];
                __nv_bfloat16 h0 = __float2bfloat16(v0);
                __nv_bfloat16 h1 = __float2bfloat16(v1);
                size_t off = (size_t)(b * SQ + q0 + row) * DD + h * 64 + d;
                *(__nv_bfloat162*)(g_ah + off) = __nv_bfloat162(h0, h1);
                *(__nv_bfloat162*)(g_al + off) = __floats2bfloat162_rn(
                    v0 - __bfloat162float(h0), v1 - __bfloat162float(h1));
            }
        }
    }
}

// ============================================================
// Launch
// ============================================================
extern "C" void kernel_launch(void* const* d_in, const int* in_sizes, int n_in,
                              void* d_out, int out_size)
{
    const float* x    = (const float*)d_in[0];
    const float* traj = (const float*)d_in[1];
    const float* Wqkv = (const float*)d_in[3];
    const float* Wout = (const float*)d_in[4];
    float* out = (float*)d_out;

    void* p;
    cudaGetSymbolAddress(&p, g_qkv);  float* qkv = (float*)p;
    cudaGetSymbolAddress(&p, g_xh);   __nv_bfloat16* xh = (__nv_bfloat16*)p;
    cudaGetSymbolAddress(&p, g_xl);   __nv_bfloat16* xl = (__nv_bfloat16*)p;
    cudaGetSymbolAddress(&p, g_ah);   __nv_bfloat16* ah = (__nv_bfloat16*)p;
    cudaGetSymbolAddress(&p, g_al);   __nv_bfloat16* al = (__nv_bfloat16*)p;
    cudaGetSymbolAddress(&p, g_wqh);  __nv_bfloat16* wqh = (__nv_bfloat16*)p;
    cudaGetSymbolAddress(&p, g_wql);  __nv_bfloat16* wql = (__nv_bfloat16*)p;
    cudaGetSymbolAddress(&p, g_woh);  __nv_bfloat16* woh = (__nv_bfloat16*)p;
    cudaGetSymbolAddress(&p, g_wol);  __nv_bfloat16* wol = (__nv_bfloat16*)p;

    // split x
    {
        int n4 = MTOK * DD / 4;
        split_kernel<<<(n4 + 255) / 256, 256>>>(
            (const float4*)x, (__nv_bfloat162*)xh, (__nv_bfloat162*)xl, n4);
    }
    // transpose+split weights
    {
        dim3 grid(3072 / 32, DD / 32);
        tsplit_kernel<<<grid, dim3(32, 8)>>>(Wqkv, wqh, wql, DD, 3072);
    }
    {
        dim3 grid(DD / 32, DD / 32);
        tsplit_kernel<<<grid, dim3(32, 8)>>>(Wout, woh, wol, DD, DD);
    }
    // GEMM1: qkv = x @ W_qkv
    {
        cudaFuncSetAttribute(gemm_bf16x3,
            cudaFuncAttributeMaxDynamicSharedMemorySize, GEMM_SMEM);
        dim3 grid(3072 / 128, MTOK / 128);
        gemm_bf16x3<<<grid, 512, GEMM_SMEM>>>(xh, xl, wqh, wql, qkv, MTOK, 3072, DD);
    }
    // attention
    {
        cudaFuncSetAttribute(attn_kernel,
            cudaFuncAttributeMaxDynamicSharedMemorySize, ATTN_SMEM);
        dim3 grid(SQ / 64, NH, BB);
        attn_kernel<<<grid, 256, ATTN_SMEM>>>(traj);
    }
    // GEMM2: out = att @ W_out
    {
        dim3 grid(DD / 128, MTOK / 128);
        gemm_bf16x3<<<grid, 512, GEMM_SMEM>>>(ah, al, woh, wol, out, MTOK, DD, DD);
    }
}

// round 9
// speedup vs baseline: 2.7038x; 1.1121x over previous
#include <cuda_runtime.h>
#include <cuda_bf16.h>
#include <cuda_fp16.h>
#include <math.h>
#include <stdint.h>

#define SQ   2048
#define NH   16
#define DD   1024
#define BB   2
#define MTOK 4096

// Scratch
__device__ float g_qkv[(size_t)MTOK * 3072];
__device__ __nv_bfloat16 g_xh[(size_t)MTOK * DD];
__device__ __nv_bfloat16 g_xl[(size_t)MTOK * DD];
__device__ __nv_bfloat16 g_ah[(size_t)MTOK * DD];
__device__ __nv_bfloat16 g_al[(size_t)MTOK * DD];
__device__ __nv_bfloat16 g_wqh[(size_t)3072 * DD];
__device__ __nv_bfloat16 g_wql[(size_t)3072 * DD];
__device__ __nv_bfloat16 g_woh[(size_t)DD * DD];
__device__ __nv_bfloat16 g_wol[(size_t)DD * DD];

// ---------------- helpers ----------------
__device__ __forceinline__ uint32_t smem_u32(const void* p) {
    uint32_t a;
    asm("{ .reg .u64 t; cvta.to.shared.u64 t, %1; cvt.u32.u64 %0, t; }" : "=r"(a) : "l"(p));
    return a;
}
__device__ __forceinline__ void cpasync16(uint32_t dst, const void* src) {
    asm volatile("cp.async.cg.shared.global [%0], [%1], 16;\n" :: "r"(dst), "l"(src));
}
#define CP_COMMIT() asm volatile("cp.async.commit_group;\n" ::: "memory")
#define SWZ128(o) ((o) ^ (((o) >> 3) & 0x70))

__device__ __forceinline__ void ldsm4(uint32_t* r, uint32_t addr) {
    asm volatile("ldmatrix.sync.aligned.m8n8.x4.shared.b16 {%0,%1,%2,%3}, [%4];"
        : "=r"(r[0]), "=r"(r[1]), "=r"(r[2]), "=r"(r[3]) : "r"(addr));
}
__device__ __forceinline__ void mma_bf16(float* c, const uint32_t* a, const uint32_t* b) {
    asm volatile(
        "mma.sync.aligned.m16n8k16.row.col.f32.bf16.bf16.f32 "
        "{%0,%1,%2,%3}, {%4,%5,%6,%7}, {%8,%9}, {%0,%1,%2,%3};"
        : "+f"(c[0]), "+f"(c[1]), "+f"(c[2]), "+f"(c[3])
        : "r"(a[0]), "r"(a[1]), "r"(a[2]), "r"(a[3]), "r"(b[0]), "r"(b[1]));
}
__device__ __forceinline__ void mma_f16(float* c, const uint32_t* a, const uint32_t* b) {
    asm volatile(
        "mma.sync.aligned.m16n8k16.row.col.f32.f16.f16.f32 "
        "{%0,%1,%2,%3}, {%4,%5,%6,%7}, {%8,%9}, {%0,%1,%2,%3};"
        : "+f"(c[0]), "+f"(c[1]), "+f"(c[2]), "+f"(c[3])
        : "r"(a[0]), "r"(a[1]), "r"(a[2]), "r"(a[3]), "r"(b[0]), "r"(b[1]));
}

// ---------------- split kernels ----------------
__global__ __launch_bounds__(256) void split_kernel(
    const float4* __restrict__ in,
    __nv_bfloat162* __restrict__ hi, __nv_bfloat162* __restrict__ lo, int n4)
{
    int i = blockIdx.x * blockDim.x + threadIdx.x;
    if (i >= n4) return;
    float4 v = in[i];
    __nv_bfloat16 hx = __float2bfloat16(v.x);
    __nv_bfloat16 hy = __float2bfloat16(v.y);
    __nv_bfloat16 hz = __float2bfloat16(v.z);
    __nv_bfloat16 hw = __float2bfloat16(v.w);
    hi[2*i+0] = __nv_bfloat162(hx, hy);
    hi[2*i+1] = __nv_bfloat162(hz, hw);
    lo[2*i+0] = __floats2bfloat162_rn(v.x - __bfloat162float(hx), v.y - __bfloat162float(hy));
    lo[2*i+1] = __floats2bfloat162_rn(v.z - __bfloat162float(hz), v.w - __bfloat162float(hw));
}

__global__ __launch_bounds__(256) void tsplit_kernel(
    const float* __restrict__ B,
    __nv_bfloat16* __restrict__ Bht, __nv_bfloat16* __restrict__ Blt,
    int K, int N)
{
    __shared__ float t[32][33];
    int n0 = blockIdx.x * 32, k0 = blockIdx.y * 32;
    for (int j = threadIdx.y; j < 32; j += 8)
        t[j][threadIdx.x] = B[(size_t)(k0 + j) * N + n0 + threadIdx.x];
    __syncthreads();
    for (int j = threadIdx.y; j < 32; j += 8) {
        float v = t[threadIdx.x][j];
        __nv_bfloat16 h = __float2bfloat16(v);
        size_t o = (size_t)(n0 + j) * K + k0 + threadIdx.x;
        Bht[o] = h;
        Blt[o] = __float2bfloat16(v - __bfloat162float(h));
    }
}

// ============================================================
// bf16x3 fused GEMM. 512 thr, 4x4 warps (32x32 tiles), BK=64,
// 3-stage cp.async, SW128 smem, fragment double-buffer across ks.
// ============================================================
#define GT_AH  0
#define GT_AL  16384
#define GT_BH  32768
#define GT_BL  49152
#define GSTGB  65536
#define GEMM_SMEM (3 * GSTGB + 1024)

__global__ __launch_bounds__(512) void gemm_bf16x3(
    const __nv_bfloat16* __restrict__ Ah, const __nv_bfloat16* __restrict__ Al,
    const __nv_bfloat16* __restrict__ Bh, const __nv_bfloat16* __restrict__ Bl,
    float* __restrict__ C, int M, int N, int K)
{
    extern __shared__ char gsm[];
    const uint32_t sbase = (smem_u32(gsm) + 1023u) & ~1023u;

    const int tid  = threadIdx.x;
    const int lane = tid & 31, wid = tid >> 5;
    const int wm   = wid >> 2, wn = wid & 3;     // 4x4 warps, warp tile 32x32
    const int g    = lane >> 2, t = lane & 3;
    const int row0 = blockIdx.y * 128;
    const int col0 = blockIdx.x * 128;
    const int nch  = K >> 6;

    const int aRow = lane & 15;
    const int aK   = (lane & 16) ? 8 : 0;
    const int bRow = (lane & 7) + ((lane & 16) ? 8 : 0);
    const int bK   = lane & 8;

    float acc[2][4][4];
    #pragma unroll
    for (int mt = 0; mt < 2; mt++)
        #pragma unroll
        for (int nt = 0; nt < 4; nt++)
            #pragma unroll
            for (int e = 0; e < 4; e++) acc[mt][nt][e] = 0.0f;

    auto load_chunk = [&](int c, int s) {
        const uint32_t base = sbase + (uint32_t)s * GSTGB;
        const int kk = c * 64;
        #pragma unroll
        for (int i = 0; i < 2; i++) {
            int u = tid + i * 512;
            int r = u >> 3, sg = u & 7;
            uint32_t so = SWZ128((uint32_t)(r * 128 + sg * 16));
            size_t goA = (size_t)(row0 + r) * K + kk + sg * 8;
            size_t goB = (size_t)(col0 + r) * K + kk + sg * 8;
            cpasync16(base + GT_AH + so, Ah + goA);
            cpasync16(base + GT_AL + so, Al + goA);
            cpasync16(base + GT_BH + so, Bh + goB);
            cpasync16(base + GT_BL + so, Bl + goB);
        }
    };

    load_chunk(0, 0); CP_COMMIT();
    if (nch > 1) { load_chunk(1, 1); CP_COMMIT(); }

    // fragment double buffers
    uint32_t afh[2][2][4], afl[2][2][4], bfh[2][2][4], bfl[2][2][4];

    int buf = 0;
    for (int c = 0; c < nch; c++) {
        if (c < nch - 1) asm volatile("cp.async.wait_group 1;\n" ::: "memory");
        else             asm volatile("cp.async.wait_group 0;\n" ::: "memory");
        __syncthreads();

        if (c + 2 < nch) {
            int s = buf - 1; if (s < 0) s += 3;
            load_chunk(c + 2, s);
            CP_COMMIT();
        }

        const uint32_t bAH = sbase + (uint32_t)buf * GSTGB + GT_AH;
        const uint32_t bAL = bAH + (GT_AL - GT_AH);
        const uint32_t bBH = bAH + (GT_BH - GT_AH);
        const uint32_t bBL = bAH + (GT_BL - GT_AH);

        // prime ks=0 fragments
        {
            #pragma unroll
            for (int mt = 0; mt < 2; mt++) {
                uint32_t so = SWZ128((uint32_t)((wm*32 + mt*16 + aRow) * 128 + aK * 2));
                ldsm4(afh[0][mt], bAH + so);
                ldsm4(afl[0][mt], bAL + so);
            }
            #pragma unroll
            for (int p = 0; p < 2; p++) {
                uint32_t so = SWZ128((uint32_t)((wn*32 + p*16 + bRow) * 128 + bK * 2));
                ldsm4(bfh[0][p], bBH + so);
                ldsm4(bfl[0][p], bBL + so);
            }
        }

        #pragma unroll
        for (int ks = 0; ks < 4; ks++) {
            const int cur = ks & 1, nxt = cur ^ 1;
            if (ks < 3) {
                const int kb = (ks + 1) * 16;
                #pragma unroll
                for (int mt = 0; mt < 2; mt++) {
                    uint32_t so = SWZ128((uint32_t)((wm*32 + mt*16 + aRow) * 128 + (kb + aK) * 2));
                    ldsm4(afh[nxt][mt], bAH + so);
                    ldsm4(afl[nxt][mt], bAL + so);
                }
                #pragma unroll
                for (int p = 0; p < 2; p++) {
                    uint32_t so = SWZ128((uint32_t)((wn*32 + p*16 + bRow) * 128 + (kb + bK) * 2));
                    ldsm4(bfh[nxt][p], bBH + so);
                    ldsm4(bfl[nxt][p], bBL + so);
                }
            }
            #pragma unroll
            for (int mt = 0; mt < 2; mt++) {
                #pragma unroll
                for (int nt = 0; nt < 4; nt++) {
                    const uint32_t* bh = &bfh[cur][nt >> 1][(nt & 1) * 2];
                    const uint32_t* bl = &bfl[cur][nt >> 1][(nt & 1) * 2];
                    mma_bf16(acc[mt][nt], afh[cur][mt], bh);
                    mma_bf16(acc[mt][nt], afh[cur][mt], bl);
                    mma_bf16(acc[mt][nt], afl[cur][mt], bh);
                }
            }
        }

        if (++buf == 3) buf = 0;
    }

    #pragma unroll
    for (int mt = 0; mt < 2; mt++) {
        #pragma unroll
        for (int nt = 0; nt < 4; nt++) {
            int r  = row0 + wm * 32 + mt * 16 + g;
            int cc = col0 + wn * 32 + nt * 8 + 2 * t;
            *(float2*)&C[(size_t)r * N + cc]       = make_float2(acc[mt][nt][0], acc[mt][nt][1]);
            *(float2*)&C[(size_t)(r + 8) * N + cc] = make_float2(acc[mt][nt][2], acc[mt][nt][3]);
        }
    }
}

// ============================================================
// Banded attention, 512 threads, fp16 split mma + bias prefetch.
// ============================================================
#define QP   72
#define VP   200
#define PSP  196
#define OF_QH  0
#define OF_QL  9216
#define OF_KH  18432
#define OF_KL  46080
#define OF_VH  73728
#define OF_VL  99328
#define OF_PS  124928
#define OF_PH  0
#define OF_PL  25600
#define ATTN_SMEM (124928 + 64*PSP*4)

__global__ __launch_bounds__(512) void attn_kernel(const float* __restrict__ traj)
{
    extern __shared__ char asmem[];
    half*  Qh = (half*)(asmem + OF_QH);
    half*  Ql = (half*)(asmem + OF_QL);
    half*  Kh = (half*)(asmem + OF_KH);
    half*  Kl = (half*)(asmem + OF_KL);
    half*  Vh = (half*)(asmem + OF_VH);
    half*  Vl = (half*)(asmem + OF_VL);
    float* Ps = (float*)(asmem + OF_PS);
    half*  Ph = (half*)(asmem + OF_PH);
    half*  Pl = (half*)(asmem + OF_PL);

    const int tid  = threadIdx.x;
    const int lane = tid & 31, wid = tid >> 5;
    const int wm   = wid >> 2, wn = wid & 3;   // 4x4 warp grid
    const int g    = lane >> 2, t = lane & 3;
    const int b = blockIdx.z, h = blockIdx.y;
    const int q0 = blockIdx.x * 64;
    const int k0 = q0 - 128;
    const float NEGINF = __int_as_float(0xff800000);

    const int aRow = lane & 15;
    const int aK   = (lane & 16) ? 8 : 0;
    const int bRow = (lane & 7) + ((lane & 16) ? 8 : 0);
    const int bK   = lane & 8;

    const float* qkbase = g_qkv + (size_t)b * SQ * 3072;
    const float* bias = traj + (size_t)(b * NH + h) * SQ * SQ;

    // ---- prefetch bias band into Ps ----
    {
        const uint32_t psb = smem_u32(Ps);
        #pragma unroll
        for (int i = 0; i < 6; i++) {
            int u = tid + i * 512;            // 0..3071
            int row = u / 48;
            int c4  = u % 48;
            int kg  = k0 + c4 * 4;
            if (kg >= 0) {
                cpasync16(psb + (uint32_t)(row * PSP + c4 * 4) * 4,
                          bias + (size_t)(q0 + row) * SQ + kg);
            }
        }
        CP_COMMIT();
    }

    // ---- load Q/K/V with hi/lo split ----
    for (int idx = tid; idx < 64 * 64; idx += 512) {
        int r = idx >> 6, d = idx & 63;
        float v = qkbase[(size_t)(q0 + r) * 3072 + h * 64 + d];
        half hh = __float2half(v);
        Qh[r * QP + d] = hh;
        Ql[r * QP + d] = __float2half(v - __half2float(hh));
    }
    for (int idx = tid; idx < 192 * 64; idx += 512) {
        int kk = idx >> 6, d = idx & 63;
        int key = k0 + kk;
        float kv = 0.0f, vv = 0.0f;
        if (key >= 0) {
            const float* p = qkbase + (size_t)key * 3072 + 1024 + h * 64 + d;
            kv = p[0];
            vv = p[1024];
        }
        half kh = __float2half(kv);
        Kh[kk * QP + d] = kh;
        Kl[kk * QP + d] = __float2half(kv - __half2float(kh));
        half vh = __float2half(vv);
        Vh[d * VP + kk] = vh;
        Vl[d * VP + kk] = __float2half(vv - __half2float(vh));
    }
    __syncthreads();

    // ---- scores: 3-pass fp16 mma, warp tile 16x48 ----
    float acc[6][4];
    #pragma unroll
    for (int nt = 0; nt < 6; nt++)
        #pragma unroll
        for (int e = 0; e < 4; e++) acc[nt][e] = 0.0f;

    #pragma unroll
    for (int seg = 0; seg < 3; seg++) {
        uint32_t aq = smem_u32(seg == 2 ? Ql : Qh);
        uint32_t bk = smem_u32(seg == 1 ? Kl : Kh);
        #pragma unroll
        for (int ks = 0; ks < 4; ks++) {
            const int kb = ks * 16;
            uint32_t af[4], bfr[3][4];
            ldsm4(af, aq + 2u * ((wm * 16 + aRow) * QP + kb + aK));
            #pragma unroll
            for (int p = 0; p < 3; p++)
                ldsm4(bfr[p], bk + 2u * ((wn * 48 + p * 16 + bRow) * QP + kb + bK));
            #pragma unroll
            for (int nt = 0; nt < 6; nt++)
                mma_f16(acc[nt], af, &bfr[nt >> 1][(nt & 1) * 2]);
        }
    }

    asm volatile("cp.async.wait_group 0;\n" ::: "memory");
    __syncthreads();

    // ---- scale + bias(smem) + mask -> Ps ----
    {
        #pragma unroll
        for (int nt = 0; nt < 6; nt++) {
            int rl = wm * 16 + g;
            int cl = wn * 48 + nt * 8 + 2 * t;
            #pragma unroll
            for (int e = 0; e < 4; e++) {
                int row = rl + ((e & 2) ? 8 : 0);
                int col = cl + (e & 1);
                int kg = k0 + col;
                float s;
                if (kg >= 0 && col >= row && col <= row + 128)
                    s = acc[nt][e] * 0.125f + Ps[row * PSP + col];
                else
                    s = NEGINF;
                Ps[row * PSP + col] = s;
            }
        }
    }
    __syncthreads();

    // ---- softmax (8 threads/row, 24 cols each), write Ph/Pl ----
    {
        int row = tid >> 3, sub = tid & 7;
        float* prow = Ps + row * PSP + sub * 24;
        float m = NEGINF;
        #pragma unroll 8
        for (int i = 0; i < 24; i++) m = fmaxf(m, prow[i]);
        m = fmaxf(m, __shfl_xor_sync(0xffffffffu, m, 1));
        m = fmaxf(m, __shfl_xor_sync(0xffffffffu, m, 2));
        m = fmaxf(m, __shfl_xor_sync(0xffffffffu, m, 4));
        float ssum = 0.0f;
        float ebuf[24];
        #pragma unroll 8
        for (int i = 0; i < 24; i++) {
            float e = expf(prow[i] - m);
            ebuf[i] = e;
            ssum += e;
        }
        ssum += __shfl_xor_sync(0xffffffffu, ssum, 1);
        ssum += __shfl_xor_sync(0xffffffffu, ssum, 2);
        ssum += __shfl_xor_sync(0xffffffffu, ssum, 4);
        float inv = 1.0f / ssum;
        half* phrow = Ph + row * VP + sub * 24;
        half* plrow = Pl + row * VP + sub * 24;
        #pragma unroll 8
        for (int i = 0; i < 24; i++) {
            float pv = ebuf[i] * inv;
            half hh = __float2half(pv);
            phrow[i] = hh;
            plrow[i] = __float2half(pv - __half2float(hh));
        }
    }
    __syncthreads();

    // ---- O = PV: 3-pass fp16 mma, warp tile 16x16, k=192 ----
    float o[2][4];
    #pragma unroll
    for (int nt = 0; nt < 2; nt++)
        #pragma unroll
        for (int e = 0; e < 4; e++) o[nt][e] = 0.0f;

    #pragma unroll
    for (int seg = 0; seg < 3; seg++) {
        uint32_t ap = smem_u32(seg == 2 ? Pl : Ph);
        uint32_t bv = smem_u32(seg == 1 ? Vl : Vh);
        for (int ks = 0; ks < 12; ks++) {
            const int kb = ks * 16;
            uint32_t af[4], bfr[4];
            ldsm4(af, ap + 2u * ((wm * 16 + aRow) * VP + kb + aK));
            ldsm4(bfr, bv + 2u * ((wn * 16 + bRow) * VP + kb + bK));
            #pragma unroll
            for (int nt = 0; nt < 2; nt++)
                mma_f16(o[nt], af, &bfr[nt * 2]);
        }
    }

    // ---- epilogue: write bf16 hi/lo ----
    #pragma unroll
    for (int nt = 0; nt < 2; nt++) {
        int rl = wm * 16 + g;
        int d  = wn * 16 + nt * 8 + 2 * t;
        #pragma unroll
        for (int half_i = 0; half_i < 2; half_i++) {
            int row = rl + half_i * 8;
            float v0 = o[nt][half_i * 2 + 0];
            float v1 = o[nt][half_i * 2 + 1];
            __nv_bfloat16 h0 = __float2bfloat16(v0);
            __nv_bfloat16 h1 = __float2bfloat16(v1);
            size_t off = (size_t)(b * SQ + q0 + row) * DD + h * 64 + d;
            *(__nv_bfloat162*)(g_ah + off) = __nv_bfloat162(h0, h1);
            *(__nv_bfloat162*)(g_al + off) = __floats2bfloat162_rn(
                v0 - __bfloat162float(h0), v1 - __bfloat162float(h1));
        }
    }
}

// ============================================================
// Launch
// ============================================================
extern "C" void kernel_launch(void* const* d_in, const int* in_sizes, int n_in,
                              void* d_out, int out_size)
{
    const float* x    = (const float*)d_in[0];
    const float* traj = (const float*)d_in[1];
    const float* Wqkv = (const float*)d_in[3];
    const float* Wout = (const float*)d_in[4];
    float* out = (float*)d_out;

    void* p;
    cudaGetSymbolAddress(&p, g_qkv);  float* qkv = (float*)p;
    cudaGetSymbolAddress(&p, g_xh);   __nv_bfloat16* xh = (__nv_bfloat16*)p;
    cudaGetSymbolAddress(&p, g_xl);   __nv_bfloat16* xl = (__nv_bfloat16*)p;
    cudaGetSymbolAddress(&p, g_ah);   __nv_bfloat16* ah = (__nv_bfloat16*)p;
    cudaGetSymbolAddress(&p, g_al);   __nv_bfloat16* al = (__nv_bfloat16*)p;
    cudaGetSymbolAddress(&p, g_wqh);  __nv_bfloat16* wqh = (__nv_bfloat16*)p;
    cudaGetSymbolAddress(&p, g_wql);  __nv_bfloat16* wql = (__nv_bfloat16*)p;
    cudaGetSymbolAddress(&p, g_woh);  __nv_bfloat16* woh = (__nv_bfloat16*)p;
    cudaGetSymbolAddress(&p, g_wol);  __nv_bfloat16* wol = (__nv_bfloat16*)p;

    // split x
    {
        int n4 = MTOK * DD / 4;
        split_kernel<<<(n4 + 255) / 256, 256>>>(
            (const float4*)x, (__nv_bfloat162*)xh, (__nv_bfloat162*)xl, n4);
    }
    // transpose+split weights
    {
        dim3 grid(3072 / 32, DD / 32);
        tsplit_kernel<<<grid, dim3(32, 8)>>>(Wqkv, wqh, wql, DD, 3072);
    }
    {
        dim3 grid(DD / 32, DD / 32);
        tsplit_kernel<<<grid, dim3(32, 8)>>>(Wout, woh, wol, DD, DD);
    }
    // GEMM1: qkv = x @ W_qkv
    {
        cudaFuncSetAttribute(gemm_bf16x3,
            cudaFuncAttributeMaxDynamicSharedMemorySize, GEMM_SMEM);
        dim3 grid(3072 / 128, MTOK / 128);
        gemm_bf16x3<<<grid, 512, GEMM_SMEM>>>(xh, xl, wqh, wql, qkv, MTOK, 3072, DD);
    }
    // attention
    {
        cudaFuncSetAttribute(attn_kernel,
            cudaFuncAttributeMaxDynamicSharedMemorySize, ATTN_SMEM);
        dim3 grid(SQ / 64, NH, BB);
        attn_kernel<<<grid, 512, ATTN_SMEM>>>(traj);
    }
    // GEMM2: out = att @ W_out
    {
        dim3 grid(DD / 128, MTOK / 128);
        gemm_bf16x3<<<grid, 512, GEMM_SMEM>>>(ah, al, woh, wol, out, MTOK, DD, DD);
    }
}

// round 10
// speedup vs baseline: 2.7853x; 1.0302x over previous
#include <cuda_runtime.h>
#include <cuda_bf16.h>
#include <cuda_fp16.h>
#include <math.h>
#include <stdint.h>

#define SQ   2048
#define NH   16
#define DD   1024
#define BB   2
#define MTOK 4096

// Scratch
__device__ float g_qkv[(size_t)MTOK * 3072];
__device__ __nv_bfloat16 g_xh[(size_t)MTOK * DD];
__device__ __nv_bfloat16 g_xl[(size_t)MTOK * DD];
__device__ __nv_bfloat16 g_ah[(size_t)MTOK * DD];
__device__ __nv_bfloat16 g_al[(size_t)MTOK * DD];
__device__ __nv_bfloat16 g_wqh[(size_t)3072 * DD];
__device__ __nv_bfloat16 g_wql[(size_t)3072 * DD];
__device__ __nv_bfloat16 g_woh[(size_t)DD * DD];
__device__ __nv_bfloat16 g_wol[(size_t)DD * DD];

// ---------------- helpers ----------------
__device__ __forceinline__ uint32_t smem_u32(const void* p) {
    uint32_t a;
    asm("{ .reg .u64 t; cvta.to.shared.u64 t, %1; cvt.u32.u64 %0, t; }" : "=r"(a) : "l"(p));
    return a;
}
__device__ __forceinline__ void cpasync16(uint32_t dst, const void* src) {
    asm volatile("cp.async.cg.shared.global [%0], [%1], 16;\n" :: "r"(dst), "l"(src));
}
#define CP_COMMIT() asm volatile("cp.async.commit_group;\n" ::: "memory")
#define SWZ128(o) ((o) ^ (((o) >> 3) & 0x70))

__device__ __forceinline__ void ldsm4(uint32_t* r, uint32_t addr) {
    asm volatile("ldmatrix.sync.aligned.m8n8.x4.shared.b16 {%0,%1,%2,%3}, [%4];"
        : "=r"(r[0]), "=r"(r[1]), "=r"(r[2]), "=r"(r[3]) : "r"(addr));
}
__device__ __forceinline__ void mma_bf16(float* c, const uint32_t* a, const uint32_t* b) {
    asm volatile(
        "mma.sync.aligned.m16n8k16.row.col.f32.bf16.bf16.f32 "
        "{%0,%1,%2,%3}, {%4,%5,%6,%7}, {%8,%9}, {%0,%1,%2,%3};"
        : "+f"(c[0]), "+f"(c[1]), "+f"(c[2]), "+f"(c[3])
        : "r"(a[0]), "r"(a[1]), "r"(a[2]), "r"(a[3]), "r"(b[0]), "r"(b[1]));
}
__device__ __forceinline__ void mma_f16(float* c, const uint32_t* a, const uint32_t* b) {
    asm volatile(
        "mma.sync.aligned.m16n8k16.row.col.f32.f16.f16.f32 "
        "{%0,%1,%2,%3}, {%4,%5,%6,%7}, {%8,%9}, {%0,%1,%2,%3};"
        : "+f"(c[0]), "+f"(c[1]), "+f"(c[2]), "+f"(c[3])
        : "r"(a[0]), "r"(a[1]), "r"(a[2]), "r"(a[3]), "r"(b[0]), "r"(b[1]));
}

// ---------------- split kernels ----------------
__global__ __launch_bounds__(256) void split_kernel(
    const float4* __restrict__ in,
    __nv_bfloat162* __restrict__ hi, __nv_bfloat162* __restrict__ lo, int n4)
{
    int i = blockIdx.x * blockDim.x + threadIdx.x;
    if (i >= n4) return;
    float4 v = in[i];
    __nv_bfloat16 hx = __float2bfloat16(v.x);
    __nv_bfloat16 hy = __float2bfloat16(v.y);
    __nv_bfloat16 hz = __float2bfloat16(v.z);
    __nv_bfloat16 hw = __float2bfloat16(v.w);
    hi[2*i+0] = __nv_bfloat162(hx, hy);
    hi[2*i+1] = __nv_bfloat162(hz, hw);
    lo[2*i+0] = __floats2bfloat162_rn(v.x - __bfloat162float(hx), v.y - __bfloat162float(hy));
    lo[2*i+1] = __floats2bfloat162_rn(v.z - __bfloat162float(hz), v.w - __bfloat162float(hw));
}

__global__ __launch_bounds__(256) void tsplit_kernel(
    const float* __restrict__ B,
    __nv_bfloat16* __restrict__ Bht, __nv_bfloat16* __restrict__ Blt,
    int K, int N)
{
    __shared__ float t[32][33];
    int n0 = blockIdx.x * 32, k0 = blockIdx.y * 32;
    for (int j = threadIdx.y; j < 32; j += 8)
        t[j][threadIdx.x] = B[(size_t)(k0 + j) * N + n0 + threadIdx.x];
    __syncthreads();
    for (int j = threadIdx.y; j < 32; j += 8) {
        float v = t[threadIdx.x][j];
        __nv_bfloat16 h = __float2bfloat16(v);
        size_t o = (size_t)(n0 + j) * K + k0 + threadIdx.x;
        Bht[o] = h;
        Blt[o] = __float2bfloat16(v - __bfloat162float(h));
    }
}

// ============================================================
// bf16x3 fused GEMM. Tile 256(M)x128(N), BK=64, 512 thr,
// 4x4 warp grid, warp tile 64x32. 2-stage cp.async, SW128 smem.
// Per ks: 12 ldsm4, 48 HMMA (4:1 MMA:LDSM).
// ============================================================
#define GT_AH  0
#define GT_AL  32768
#define GT_BH  65536
#define GT_BL  81920
#define GSTGB  98304
#define GEMM_SMEM (2 * GSTGB + 1024)

__global__ __launch_bounds__(512) void gemm_bf16x3(
    const __nv_bfloat16* __restrict__ Ah, const __nv_bfloat16* __restrict__ Al,
    const __nv_bfloat16* __restrict__ Bh, const __nv_bfloat16* __restrict__ Bl,
    float* __restrict__ C, int M, int N, int K)
{
    extern __shared__ char gsm[];
    const uint32_t sbase = (smem_u32(gsm) + 1023u) & ~1023u;

    const int tid  = threadIdx.x;
    const int lane = tid & 31, wid = tid >> 5;
    const int wm   = wid >> 2, wn = wid & 3;     // 4x4 warps, warp tile 64x32
    const int g    = lane >> 2, t = lane & 3;
    const int row0 = blockIdx.y * 256;
    const int col0 = blockIdx.x * 128;
    const int nch  = K >> 6;

    const int aRow = lane & 15;
    const int aK   = (lane & 16) ? 8 : 0;
    const int bRow = (lane & 7) + ((lane & 16) ? 8 : 0);
    const int bK   = lane & 8;

    float acc[4][4][4];
    #pragma unroll
    for (int mt = 0; mt < 4; mt++)
        #pragma unroll
        for (int nt = 0; nt < 4; nt++)
            #pragma unroll
            for (int e = 0; e < 4; e++) acc[mt][nt][e] = 0.0f;

    auto load_chunk = [&](int c, int s) {
        const uint32_t base = sbase + (uint32_t)s * GSTGB;
        const int kk = c * 64;
        // A: 256 rows x 64 k, hi+lo
        #pragma unroll
        for (int i = 0; i < 4; i++) {
            int u = tid + i * 512;              // 0..2047
            int r = u >> 3, sg = u & 7;
            uint32_t so = SWZ128((uint32_t)(r * 128 + sg * 16));
            size_t go = (size_t)(row0 + r) * K + kk + sg * 8;
            cpasync16(base + GT_AH + so, Ah + go);
            cpasync16(base + GT_AL + so, Al + go);
        }
        // B: 128 rows x 64 k, hi+lo
        #pragma unroll
        for (int i = 0; i < 2; i++) {
            int u = tid + i * 512;              // 0..1023
            int r = u >> 3, sg = u & 7;
            uint32_t so = SWZ128((uint32_t)(r * 128 + sg * 16));
            size_t go = (size_t)(col0 + r) * K + kk + sg * 8;
            cpasync16(base + GT_BH + so, Bh + go);
            cpasync16(base + GT_BL + so, Bl + go);
        }
    };

    load_chunk(0, 0); CP_COMMIT();

    for (int c = 0; c < nch; c++) {
        const int buf = c & 1;
        if (c + 1 < nch) { load_chunk(c + 1, buf ^ 1); CP_COMMIT(); }
        if (c + 1 < nch) asm volatile("cp.async.wait_group 1;\n" ::: "memory");
        else             asm volatile("cp.async.wait_group 0;\n" ::: "memory");
        __syncthreads();

        const uint32_t bAH = sbase + (uint32_t)buf * GSTGB + GT_AH;
        const uint32_t bAL = bAH + (GT_AL - GT_AH);
        const uint32_t bBH = bAH + (GT_BH - GT_AH);
        const uint32_t bBL = bAH + (GT_BL - GT_AH);

        #pragma unroll
        for (int ks = 0; ks < 4; ks++) {
            const int kb = ks * 16;
            uint32_t afh[4][4], afl[4][4], bfh[2][4], bfl[2][4];
            #pragma unroll
            for (int mt = 0; mt < 4; mt++) {
                uint32_t so = SWZ128((uint32_t)((wm*64 + mt*16 + aRow) * 128 + (kb + aK) * 2));
                ldsm4(afh[mt], bAH + so);
                ldsm4(afl[mt], bAL + so);
            }
            #pragma unroll
            for (int p = 0; p < 2; p++) {
                uint32_t so = SWZ128((uint32_t)((wn*32 + p*16 + bRow) * 128 + (kb + bK) * 2));
                ldsm4(bfh[p], bBH + so);
                ldsm4(bfl[p], bBL + so);
            }
            #pragma unroll
            for (int mt = 0; mt < 4; mt++) {
                #pragma unroll
                for (int nt = 0; nt < 4; nt++) {
                    const uint32_t* bh = &bfh[nt >> 1][(nt & 1) * 2];
                    const uint32_t* bl = &bfl[nt >> 1][(nt & 1) * 2];
                    mma_bf16(acc[mt][nt], afh[mt], bh);
                    mma_bf16(acc[mt][nt], afh[mt], bl);
                    mma_bf16(acc[mt][nt], afl[mt], bh);
                }
            }
        }
        __syncthreads();   // all warps done with buf before next load overwrites it
    }

    #pragma unroll
    for (int mt = 0; mt < 4; mt++) {
        #pragma unroll
        for (int nt = 0; nt < 4; nt++) {
            int r  = row0 + wm * 64 + mt * 16 + g;
            int cc = col0 + wn * 32 + nt * 8 + 2 * t;
            *(float2*)&C[(size_t)r * N + cc]       = make_float2(acc[mt][nt][0], acc[mt][nt][1]);
            *(float2*)&C[(size_t)(r + 8) * N + cc] = make_float2(acc[mt][nt][2], acc[mt][nt][3]);
        }
    }
}

// ============================================================
// Banded attention, 512 threads, fp16 split mma + bias prefetch
// (unchanged from R9).
// ============================================================
#define QP   72
#define VP   200
#define PSP  196
#define OF_QH  0
#define OF_QL  9216
#define OF_KH  18432
#define OF_KL  46080
#define OF_VH  73728
#define OF_VL  99328
#define OF_PS  124928
#define OF_PH  0
#define OF_PL  25600
#define ATTN_SMEM (124928 + 64*PSP*4)

__global__ __launch_bounds__(512) void attn_kernel(const float* __restrict__ traj)
{
    extern __shared__ char asmem[];
    half*  Qh = (half*)(asmem + OF_QH);
    half*  Ql = (half*)(asmem + OF_QL);
    half*  Kh = (half*)(asmem + OF_KH);
    half*  Kl = (half*)(asmem + OF_KL);
    half*  Vh = (half*)(asmem + OF_VH);
    half*  Vl = (half*)(asmem + OF_VL);
    float* Ps = (float*)(asmem + OF_PS);
    half*  Ph = (half*)(asmem + OF_PH);
    half*  Pl = (half*)(asmem + OF_PL);

    const int tid  = threadIdx.x;
    const int lane = tid & 31, wid = tid >> 5;
    const int wm   = wid >> 2, wn = wid & 3;
    const int g    = lane >> 2, t = lane & 3;
    const int b = blockIdx.z, h = blockIdx.y;
    const int q0 = blockIdx.x * 64;
    const int k0 = q0 - 128;
    const float NEGINF = __int_as_float(0xff800000);

    const int aRow = lane & 15;
    const int aK   = (lane & 16) ? 8 : 0;
    const int bRow = (lane & 7) + ((lane & 16) ? 8 : 0);
    const int bK   = lane & 8;

    const float* qkbase = g_qkv + (size_t)b * SQ * 3072;
    const float* bias = traj + (size_t)(b * NH + h) * SQ * SQ;

    // ---- prefetch bias band into Ps ----
    {
        const uint32_t psb = smem_u32(Ps);
        #pragma unroll
        for (int i = 0; i < 6; i++) {
            int u = tid + i * 512;
            int row = u / 48;
            int c4  = u % 48;
            int kg  = k0 + c4 * 4;
            if (kg >= 0) {
                cpasync16(psb + (uint32_t)(row * PSP + c4 * 4) * 4,
                          bias + (size_t)(q0 + row) * SQ + kg);
            }
        }
        CP_COMMIT();
    }

    // ---- load Q/K/V with hi/lo split ----
    for (int idx = tid; idx < 64 * 64; idx += 512) {
        int r = idx >> 6, d = idx & 63;
        float v = qkbase[(size_t)(q0 + r) * 3072 + h * 64 + d];
        half hh = __float2half(v);
        Qh[r * QP + d] = hh;
        Ql[r * QP + d] = __float2half(v - __half2float(hh));
    }
    for (int idx = tid; idx < 192 * 64; idx += 512) {
        int kk = idx >> 6, d = idx & 63;
        int key = k0 + kk;
        float kv = 0.0f, vv = 0.0f;
        if (key >= 0) {
            const float* p = qkbase + (size_t)key * 3072 + 1024 + h * 64 + d;
            kv = p[0];
            vv = p[1024];
        }
        half kh = __float2half(kv);
        Kh[kk * QP + d] = kh;
        Kl[kk * QP + d] = __float2half(kv - __half2float(kh));
        half vh = __float2half(vv);
        Vh[d * VP + kk] = vh;
        Vl[d * VP + kk] = __float2half(vv - __half2float(vh));
    }
    __syncthreads();

    // ---- scores: 3-pass fp16 mma, warp tile 16x48 ----
    float acc[6][4];
    #pragma unroll
    for (int nt = 0; nt < 6; nt++)
        #pragma unroll
        for (int e = 0; e < 4; e++) acc[nt][e] = 0.0f;

    #pragma unroll
    for (int seg = 0; seg < 3; seg++) {
        uint32_t aq = smem_u32(seg == 2 ? Ql : Qh);
        uint32_t bk = smem_u32(seg == 1 ? Kl : Kh);
        #pragma unroll
        for (int ks = 0; ks < 4; ks++) {
            const int kb = ks * 16;
            uint32_t af[4], bfr[3][4];
            ldsm4(af, aq + 2u * ((wm * 16 + aRow) * QP + kb + aK));
            #pragma unroll
            for (int p = 0; p < 3; p++)
                ldsm4(bfr[p], bk + 2u * ((wn * 48 + p * 16 + bRow) * QP + kb + bK));
            #pragma unroll
            for (int nt = 0; nt < 6; nt++)
                mma_f16(acc[nt], af, &bfr[nt >> 1][(nt & 1) * 2]);
        }
    }

    asm volatile("cp.async.wait_group 0;\n" ::: "memory");
    __syncthreads();

    // ---- scale + bias(smem) + mask -> Ps ----
    {
        #pragma unroll
        for (int nt = 0; nt < 6; nt++) {
            int rl = wm * 16 + g;
            int cl = wn * 48 + nt * 8 + 2 * t;
            #pragma unroll
            for (int e = 0; e < 4; e++) {
                int row = rl + ((e & 2) ? 8 : 0);
                int col = cl + (e & 1);
                int kg = k0 + col;
                float s;
                if (kg >= 0 && col >= row && col <= row + 128)
                    s = acc[nt][e] * 0.125f + Ps[row * PSP + col];
                else
                    s = NEGINF;
                Ps[row * PSP + col] = s;
            }
        }
    }
    __syncthreads();

    // ---- softmax (8 threads/row), write Ph/Pl ----
    {
        int row = tid >> 3, sub = tid & 7;
        float* prow = Ps + row * PSP + sub * 24;
        float m = NEGINF;
        #pragma unroll 8
        for (int i = 0; i < 24; i++) m = fmaxf(m, prow[i]);
        m = fmaxf(m, __shfl_xor_sync(0xffffffffu, m, 1));
        m = fmaxf(m, __shfl_xor_sync(0xffffffffu, m, 2));
        m = fmaxf(m, __shfl_xor_sync(0xffffffffu, m, 4));
        float ssum = 0.0f;
        float ebuf[24];
        #pragma unroll 8
        for (int i = 0; i < 24; i++) {
            float e = expf(prow[i] - m);
            ebuf[i] = e;
            ssum += e;
        }
        ssum += __shfl_xor_sync(0xffffffffu, ssum, 1);
        ssum += __shfl_xor_sync(0xffffffffu, ssum, 2);
        ssum += __shfl_xor_sync(0xffffffffu, ssum, 4);
        float inv = 1.0f / ssum;
        half* phrow = Ph + row * VP + sub * 24;
        half* plrow = Pl + row * VP + sub * 24;
        #pragma unroll 8
        for (int i = 0; i < 24; i++) {
            float pv = ebuf[i] * inv;
            half hh = __float2half(pv);
            phrow[i] = hh;
            plrow[i] = __float2half(pv - __half2float(hh));
        }
    }
    __syncthreads();

    // ---- O = PV: 3-pass fp16 mma, warp tile 16x16, k=192 ----
    float o[2][4];
    #pragma unroll
    for (int nt = 0; nt < 2; nt++)
        #pragma unroll
        for (int e = 0; e < 4; e++) o[nt][e] = 0.0f;

    #pragma unroll
    for (int seg = 0; seg < 3; seg++) {
        uint32_t ap = smem_u32(seg == 2 ? Pl : Ph);
        uint32_t bv = smem_u32(seg == 1 ? Vl : Vh);
        for (int ks = 0; ks < 12; ks++) {
            const int kb = ks * 16;
            uint32_t af[4], bfr[4];
            ldsm4(af, ap + 2u * ((wm * 16 + aRow) * VP + kb + aK));
            ldsm4(bfr, bv + 2u * ((wn * 16 + bRow) * VP + kb + bK));
            #pragma unroll
            for (int nt = 0; nt < 2; nt++)
                mma_f16(o[nt], af, &bfr[nt * 2]);
        }
    }

    // ---- epilogue: write bf16 hi/lo ----
    #pragma unroll
    for (int nt = 0; nt < 2; nt++) {
        int rl = wm * 16 + g;
        int d  = wn * 16 + nt * 8 + 2 * t;
        #pragma unroll
        for (int half_i = 0; half_i < 2; half_i++) {
            int row = rl + half_i * 8;
            float v0 = o[nt][half_i * 2 + 0];
            float v1 = o[nt][half_i * 2 + 1];
            __nv_bfloat16 h0 = __float2bfloat16(v0);
            __nv_bfloat16 h1 = __float2bfloat16(v1);
            size_t off = (size_t)(b * SQ + q0 + row) * DD + h * 64 + d;
            *(__nv_bfloat162*)(g_ah + off) = __nv_bfloat162(h0, h1);
            *(__nv_bfloat162*)(g_al + off) = __floats2bfloat162_rn(
                v0 - __bfloat162float(h0), v1 - __bfloat162float(h1));
        }
    }
}

// ============================================================
// Launch
// ============================================================
extern "C" void kernel_launch(void* const* d_in, const int* in_sizes, int n_in,
                              void* d_out, int out_size)
{
    const float* x    = (const float*)d_in[0];
    const float* traj = (const float*)d_in[1];
    const float* Wqkv = (const float*)d_in[3];
    const float* Wout = (const float*)d_in[4];
    float* out = (float*)d_out;

    void* p;
    cudaGetSymbolAddress(&p, g_qkv);  float* qkv = (float*)p;
    cudaGetSymbolAddress(&p, g_xh);   __nv_bfloat16* xh = (__nv_bfloat16*)p;
    cudaGetSymbolAddress(&p, g_xl);   __nv_bfloat16* xl = (__nv_bfloat16*)p;
    cudaGetSymbolAddress(&p, g_ah);   __nv_bfloat16* ah = (__nv_bfloat16*)p;
    cudaGetSymbolAddress(&p, g_al);   __nv_bfloat16* al = (__nv_bfloat16*)p;
    cudaGetSymbolAddress(&p, g_wqh);  __nv_bfloat16* wqh = (__nv_bfloat16*)p;
    cudaGetSymbolAddress(&p, g_wql);  __nv_bfloat16* wql = (__nv_bfloat16*)p;
    cudaGetSymbolAddress(&p, g_woh);  __nv_bfloat16* woh = (__nv_bfloat16*)p;
    cudaGetSymbolAddress(&p, g_wol);  __nv_bfloat16* wol = (__nv_bfloat16*)p;

    // split x
    {
        int n4 = MTOK * DD / 4;
        split_kernel<<<(n4 + 255) / 256, 256>>>(
            (const float4*)x, (__nv_bfloat162*)xh, (__nv_bfloat162*)xl, n4);
    }
    // transpose+split weights
    {
        dim3 grid(3072 / 32, DD / 32);
        tsplit_kernel<<<grid, dim3(32, 8)>>>(Wqkv, wqh, wql, DD, 3072);
    }
    {
        dim3 grid(DD / 32, DD / 32);
        tsplit_kernel<<<grid, dim3(32, 8)>>>(Wout, woh, wol, DD, DD);
    }
    // GEMM1: qkv = x @ W_qkv
    {
        cudaFuncSetAttribute(gemm_bf16x3,
            cudaFuncAttributeMaxDynamicSharedMemorySize, GEMM_SMEM);
        dim3 grid(3072 / 128, MTOK / 256);
        gemm_bf16x3<<<grid, 512, GEMM_SMEM>>>(xh, xl, wqh, wql, qkv, MTOK, 3072, DD);
    }
    // attention
    {
        cudaFuncSetAttribute(attn_kernel,
            cudaFuncAttributeMaxDynamicSharedMemorySize, ATTN_SMEM);
        dim3 grid(SQ / 64, NH, BB);
        attn_kernel<<<grid, 512, ATTN_SMEM>>>(traj);
    }
    // GEMM2: out = att @ W_out
    {
        dim3 grid(DD / 128, MTOK / 256);
        gemm_bf16x3<<<grid, 512, GEMM_SMEM>>>(ah, al, woh, wol, out, MTOK, DD, DD);
    }
}

// round 11
// speedup vs baseline: 2.7990x; 1.0049x over previous
#include <cuda_runtime.h>
#include <cuda_bf16.h>
#include <cuda_fp16.h>
#include <math.h>
#include <stdint.h>

#define SQ   2048
#define NH   16
#define DD   1024
#define BB   2
#define MTOK 4096

// Scratch
__device__ float g_qkv[(size_t)MTOK * 3072];
__device__ __nv_bfloat16 g_xh[(size_t)MTOK * DD];
__device__ __nv_bfloat16 g_xl[(size_t)MTOK * DD];
__device__ __nv_bfloat16 g_ah[(size_t)MTOK * DD];
__device__ __nv_bfloat16 g_al[(size_t)MTOK * DD];
__device__ __nv_bfloat16 g_wqh[(size_t)3072 * DD];
__device__ __nv_bfloat16 g_wql[(size_t)3072 * DD];
__device__ __nv_bfloat16 g_woh[(size_t)DD * DD];
__device__ __nv_bfloat16 g_wol[(size_t)DD * DD];

// ---------------- helpers ----------------
__device__ __forceinline__ uint32_t smem_u32(const void* p) {
    uint32_t a;
    asm("{ .reg .u64 t; cvta.to.shared.u64 t, %1; cvt.u32.u64 %0, t; }" : "=r"(a) : "l"(p));
    return a;
}
__device__ __forceinline__ void cpasync16(uint32_t dst, const void* src) {
    asm volatile("cp.async.cg.shared.global [%0], [%1], 16;\n" :: "r"(dst), "l"(src));
}
#define CP_COMMIT() asm volatile("cp.async.commit_group;\n" ::: "memory")
#define SWZ128(o) ((o) ^ (((o) >> 3) & 0x70))

__device__ __forceinline__ void ldsm4(uint32_t* r, uint32_t addr) {
    asm volatile("ldmatrix.sync.aligned.m8n8.x4.shared.b16 {%0,%1,%2,%3}, [%4];"
        : "=r"(r[0]), "=r"(r[1]), "=r"(r[2]), "=r"(r[3]) : "r"(addr));
}
__device__ __forceinline__ void mma_bf16(float* c, const uint32_t* a, const uint32_t* b) {
    asm volatile(
        "mma.sync.aligned.m16n8k16.row.col.f32.bf16.bf16.f32 "
        "{%0,%1,%2,%3}, {%4,%5,%6,%7}, {%8,%9}, {%0,%1,%2,%3};"
        : "+f"(c[0]), "+f"(c[1]), "+f"(c[2]), "+f"(c[3])
        : "r"(a[0]), "r"(a[1]), "r"(a[2]), "r"(a[3]), "r"(b[0]), "r"(b[1]));
}
__device__ __forceinline__ void mma_f16(float* c, const uint32_t* a, const uint32_t* b) {
    asm volatile(
        "mma.sync.aligned.m16n8k16.row.col.f32.f16.f16.f32 "
        "{%0,%1,%2,%3}, {%4,%5,%6,%7}, {%8,%9}, {%0,%1,%2,%3};"
        : "+f"(c[0]), "+f"(c[1]), "+f"(c[2]), "+f"(c[3])
        : "r"(a[0]), "r"(a[1]), "r"(a[2]), "r"(a[3]), "r"(b[0]), "r"(b[1]));
}

// ---------------- split kernels ----------------
__global__ __launch_bounds__(256) void split_kernel(
    const float4* __restrict__ in,
    __nv_bfloat162* __restrict__ hi, __nv_bfloat162* __restrict__ lo, int n4)
{
    int i = blockIdx.x * blockDim.x + threadIdx.x;
    if (i >= n4) return;
    float4 v = in[i];
    __nv_bfloat16 hx = __float2bfloat16(v.x);
    __nv_bfloat16 hy = __float2bfloat16(v.y);
    __nv_bfloat16 hz = __float2bfloat16(v.z);
    __nv_bfloat16 hw = __float2bfloat16(v.w);
    hi[2*i+0] = __nv_bfloat162(hx, hy);
    hi[2*i+1] = __nv_bfloat162(hz, hw);
    lo[2*i+0] = __floats2bfloat162_rn(v.x - __bfloat162float(hx), v.y - __bfloat162float(hy));
    lo[2*i+1] = __floats2bfloat162_rn(v.z - __bfloat162float(hz), v.w - __bfloat162float(hw));
}

__global__ __launch_bounds__(256) void tsplit_kernel(
    const float* __restrict__ B,
    __nv_bfloat16* __restrict__ Bht, __nv_bfloat16* __restrict__ Blt,
    int K, int N)
{
    __shared__ float t[32][33];
    int n0 = blockIdx.x * 32, k0 = blockIdx.y * 32;
    for (int j = threadIdx.y; j < 32; j += 8)
        t[j][threadIdx.x] = B[(size_t)(k0 + j) * N + n0 + threadIdx.x];
    __syncthreads();
    for (int j = threadIdx.y; j < 32; j += 8) {
        float v = t[threadIdx.x][j];
        __nv_bfloat16 h = __float2bfloat16(v);
        size_t o = (size_t)(n0 + j) * K + k0 + threadIdx.x;
        Bht[o] = h;
        Blt[o] = __float2bfloat16(v - __bfloat162float(h));
    }
}

// ============================================================
// bf16x3 fused GEMM. Tile 256(M)x128(N), BK=64, 512 thr,
// 4x4 warp grid, warp tile 64x32. 2-stage cp.async, SW128 smem.
// Inner loop PRODUCT-OUTERMOST: consecutive HMMAs hit distinct
// accumulators (16 between same-acc revisits) to break RAW chains.
// ============================================================
#define GT_AH  0
#define GT_AL  32768
#define GT_BH  65536
#define GT_BL  81920
#define GSTGB  98304
#define GEMM_SMEM (2 * GSTGB + 1024)

__global__ __launch_bounds__(512) void gemm_bf16x3(
    const __nv_bfloat16* __restrict__ Ah, const __nv_bfloat16* __restrict__ Al,
    const __nv_bfloat16* __restrict__ Bh, const __nv_bfloat16* __restrict__ Bl,
    float* __restrict__ C, int M, int N, int K)
{
    extern __shared__ char gsm[];
    const uint32_t sbase = (smem_u32(gsm) + 1023u) & ~1023u;

    const int tid  = threadIdx.x;
    const int lane = tid & 31, wid = tid >> 5;
    const int wm   = wid >> 2, wn = wid & 3;     // 4x4 warps, warp tile 64x32
    const int g    = lane >> 2, t = lane & 3;
    const int row0 = blockIdx.y * 256;
    const int col0 = blockIdx.x * 128;
    const int nch  = K >> 6;

    const int aRow = lane & 15;
    const int aK   = (lane & 16) ? 8 : 0;
    const int bRow = (lane & 7) + ((lane & 16) ? 8 : 0);
    const int bK   = lane & 8;

    float acc[4][4][4];
    #pragma unroll
    for (int mt = 0; mt < 4; mt++)
        #pragma unroll
        for (int nt = 0; nt < 4; nt++)
            #pragma unroll
            for (int e = 0; e < 4; e++) acc[mt][nt][e] = 0.0f;

    auto load_chunk = [&](int c, int s) {
        const uint32_t base = sbase + (uint32_t)s * GSTGB;
        const int kk = c * 64;
        #pragma unroll
        for (int i = 0; i < 4; i++) {
            int u = tid + i * 512;              // 0..2047
            int r = u >> 3, sg = u & 7;
            uint32_t so = SWZ128((uint32_t)(r * 128 + sg * 16));
            size_t go = (size_t)(row0 + r) * K + kk + sg * 8;
            cpasync16(base + GT_AH + so, Ah + go);
            cpasync16(base + GT_AL + so, Al + go);
        }
        #pragma unroll
        for (int i = 0; i < 2; i++) {
            int u = tid + i * 512;              // 0..1023
            int r = u >> 3, sg = u & 7;
            uint32_t so = SWZ128((uint32_t)(r * 128 + sg * 16));
            size_t go = (size_t)(col0 + r) * K + kk + sg * 8;
            cpasync16(base + GT_BH + so, Bh + go);
            cpasync16(base + GT_BL + so, Bl + go);
        }
    };

    load_chunk(0, 0); CP_COMMIT();

    for (int c = 0; c < nch; c++) {
        const int buf = c & 1;
        if (c + 1 < nch) { load_chunk(c + 1, buf ^ 1); CP_COMMIT(); }
        if (c + 1 < nch) asm volatile("cp.async.wait_group 1;\n" ::: "memory");
        else             asm volatile("cp.async.wait_group 0;\n" ::: "memory");
        __syncthreads();

        const uint32_t bAH = sbase + (uint32_t)buf * GSTGB + GT_AH;
        const uint32_t bAL = bAH + (GT_AL - GT_AH);
        const uint32_t bBH = bAH + (GT_BH - GT_AH);
        const uint32_t bBL = bAH + (GT_BL - GT_AH);

        #pragma unroll
        for (int ks = 0; ks < 4; ks++) {
            const int kb = ks * 16;
            uint32_t afh[4][4], afl[4][4], bfh[2][4], bfl[2][4];
            #pragma unroll
            for (int mt = 0; mt < 4; mt++) {
                uint32_t so = SWZ128((uint32_t)((wm*64 + mt*16 + aRow) * 128 + (kb + aK) * 2));
                ldsm4(afh[mt], bAH + so);
                ldsm4(afl[mt], bAL + so);
            }
            #pragma unroll
            for (int p = 0; p < 2; p++) {
                uint32_t so = SWZ128((uint32_t)((wn*32 + p*16 + bRow) * 128 + (kb + bK) * 2));
                ldsm4(bfh[p], bBH + so);
                ldsm4(bfl[p], bBL + so);
            }
            // product-outermost: 16 distinct accs between same-acc revisits
            #pragma unroll
            for (int p = 0; p < 3; p++) {
                #pragma unroll
                for (int mt = 0; mt < 4; mt++) {
                    const uint32_t* a = (p < 2) ? afh[mt] : afl[mt];
                    #pragma unroll
                    for (int nt = 0; nt < 4; nt++) {
                        const uint32_t* b = (p == 1)
                            ? &bfl[nt >> 1][(nt & 1) * 2]
                            : &bfh[nt >> 1][(nt & 1) * 2];
                        mma_bf16(acc[mt][nt], a, b);
                    }
                }
            }
        }
        __syncthreads();
    }

    #pragma unroll
    for (int mt = 0; mt < 4; mt++) {
        #pragma unroll
        for (int nt = 0; nt < 4; nt++) {
            int r  = row0 + wm * 64 + mt * 16 + g;
            int cc = col0 + wn * 32 + nt * 8 + 2 * t;
            *(float2*)&C[(size_t)r * N + cc]       = make_float2(acc[mt][nt][0], acc[mt][nt][1]);
            *(float2*)&C[(size_t)(r + 8) * N + cc] = make_float2(acc[mt][nt][2], acc[mt][nt][3]);
        }
    }
}

// ============================================================
// Banded attention, 512 threads, fp16 split mma + bias prefetch
// (unchanged from R9/R10).
// ============================================================
#define QP   72
#define VP   200
#define PSP  196
#define OF_QH  0
#define OF_QL  9216
#define OF_KH  18432
#define OF_KL  46080
#define OF_VH  73728
#define OF_VL  99328
#define OF_PS  124928
#define OF_PH  0
#define OF_PL  25600
#define ATTN_SMEM (124928 + 64*PSP*4)

__global__ __launch_bounds__(512) void attn_kernel(const float* __restrict__ traj)
{
    extern __shared__ char asmem[];
    half*  Qh = (half*)(asmem + OF_QH);
    half*  Ql = (half*)(asmem + OF_QL);
    half*  Kh = (half*)(asmem + OF_KH);
    half*  Kl = (half*)(asmem + OF_KL);
    half*  Vh = (half*)(asmem + OF_VH);
    half*  Vl = (half*)(asmem + OF_VL);
    float* Ps = (float*)(asmem + OF_PS);
    half*  Ph = (half*)(asmem + OF_PH);
    half*  Pl = (half*)(asmem + OF_PL);

    const int tid  = threadIdx.x;
    const int lane = tid & 31, wid = tid >> 5;
    const int wm   = wid >> 2, wn = wid & 3;
    const int g    = lane >> 2, t = lane & 3;
    const int b = blockIdx.z, h = blockIdx.y;
    const int q0 = blockIdx.x * 64;
    const int k0 = q0 - 128;
    const float NEGINF = __int_as_float(0xff800000);

    const int aRow = lane & 15;
    const int aK   = (lane & 16) ? 8 : 0;
    const int bRow = (lane & 7) + ((lane & 16) ? 8 : 0);
    const int bK   = lane & 8;

    const float* qkbase = g_qkv + (size_t)b * SQ * 3072;
    const float* bias = traj + (size_t)(b * NH + h) * SQ * SQ;

    // ---- prefetch bias band into Ps ----
    {
        const uint32_t psb = smem_u32(Ps);
        #pragma unroll
        for (int i = 0; i < 6; i++) {
            int u = tid + i * 512;
            int row = u / 48;
            int c4  = u % 48;
            int kg  = k0 + c4 * 4;
            if (kg >= 0) {
                cpasync16(psb + (uint32_t)(row * PSP + c4 * 4) * 4,
                          bias + (size_t)(q0 + row) * SQ + kg);
            }
        }
        CP_COMMIT();
    }

    // ---- load Q/K/V with hi/lo split ----
    for (int idx = tid; idx < 64 * 64; idx += 512) {
        int r = idx >> 6, d = idx & 63;
        float v = qkbase[(size_t)(q0 + r) * 3072 + h * 64 + d];
        half hh = __float2half(v);
        Qh[r * QP + d] = hh;
        Ql[r * QP + d] = __float2half(v - __half2float(hh));
    }
    for (int idx = tid; idx < 192 * 64; idx += 512) {
        int kk = idx >> 6, d = idx & 63;
        int key = k0 + kk;
        float kv = 0.0f, vv = 0.0f;
        if (key >= 0) {
            const float* p = qkbase + (size_t)key * 3072 + 1024 + h * 64 + d;
            kv = p[0];
            vv = p[1024];
        }
        half kh = __float2half(kv);
        Kh[kk * QP + d] = kh;
        Kl[kk * QP + d] = __float2half(kv - __half2float(kh));
        half vh = __float2half(vv);
        Vh[d * VP + kk] = vh;
        Vl[d * VP + kk] = __float2half(vv - __half2float(vh));
    }
    __syncthreads();

    // ---- scores: 3-pass fp16 mma, warp tile 16x48 ----
    float acc[6][4];
    #pragma unroll
    for (int nt = 0; nt < 6; nt++)
        #pragma unroll
        for (int e = 0; e < 4; e++) acc[nt][e] = 0.0f;

    #pragma unroll
    for (int seg = 0; seg < 3; seg++) {
        uint32_t aq = smem_u32(seg == 2 ? Ql : Qh);
        uint32_t bk = smem_u32(seg == 1 ? Kl : Kh);
        #pragma unroll
        for (int ks = 0; ks < 4; ks++) {
            const int kb = ks * 16;
            uint32_t af[4], bfr[3][4];
            ldsm4(af, aq + 2u * ((wm * 16 + aRow) * QP + kb + aK));
            #pragma unroll
            for (int p = 0; p < 3; p++)
                ldsm4(bfr[p], bk + 2u * ((wn * 48 + p * 16 + bRow) * QP + kb + bK));
            #pragma unroll
            for (int nt = 0; nt < 6; nt++)
                mma_f16(acc[nt], af, &bfr[nt >> 1][(nt & 1) * 2]);
        }
    }

    asm volatile("cp.async.wait_group 0;\n" ::: "memory");
    __syncthreads();

    // ---- scale + bias(smem) + mask -> Ps ----
    {
        #pragma unroll
        for (int nt = 0; nt < 6; nt++) {
            int rl = wm * 16 + g;
            int cl = wn * 48 + nt * 8 + 2 * t;
            #pragma unroll
            for (int e = 0; e < 4; e++) {
                int row = rl + ((e & 2) ? 8 : 0);
                int col = cl + (e & 1);
                int kg = k0 + col;
                float s;
                if (kg >= 0 && col >= row && col <= row + 128)
                    s = acc[nt][e] * 0.125f + Ps[row * PSP + col];
                else
                    s = NEGINF;
                Ps[row * PSP + col] = s;
            }
        }
    }
    __syncthreads();

    // ---- softmax (8 threads/row), write Ph/Pl ----
    {
        int row = tid >> 3, sub = tid & 7;
        float* prow = Ps + row * PSP + sub * 24;
        float m = NEGINF;
        #pragma unroll 8
        for (int i = 0; i < 24; i++) m = fmaxf(m, prow[i]);
        m = fmaxf(m, __shfl_xor_sync(0xffffffffu, m, 1));
        m = fmaxf(m, __shfl_xor_sync(0xffffffffu, m, 2));
        m = fmaxf(m, __shfl_xor_sync(0xffffffffu, m, 4));
        float ssum = 0.0f;
        float ebuf[24];
        #pragma unroll 8
        for (int i = 0; i < 24; i++) {
            float e = expf(prow[i] - m);
            ebuf[i] = e;
            ssum += e;
        }
        ssum += __shfl_xor_sync(0xffffffffu, ssum, 1);
        ssum += __shfl_xor_sync(0xffffffffu, ssum, 2);
        ssum += __shfl_xor_sync(0xffffffffu, ssum, 4);
        float inv = 1.0f / ssum;
        half* phrow = Ph + row * VP + sub * 24;
        half* plrow = Pl + row * VP + sub * 24;
        #pragma unroll 8
        for (int i = 0; i < 24; i++) {
            float pv = ebuf[i] * inv;
            half hh = __float2half(pv);
            phrow[i] = hh;
            plrow[i] = __float2half(pv - __half2float(hh));
        }
    }
    __syncthreads();

    // ---- O = PV: 3-pass fp16 mma, warp tile 16x16, k=192 ----
    float o[2][4];
    #pragma unroll
    for (int nt = 0; nt < 2; nt++)
        #pragma unroll
        for (int e = 0; e < 4; e++) o[nt][e] = 0.0f;

    #pragma unroll
    for (int seg = 0; seg < 3; seg++) {
        uint32_t ap = smem_u32(seg == 2 ? Pl : Ph);
        uint32_t bv = smem_u32(seg == 1 ? Vl : Vh);
        for (int ks = 0; ks < 12; ks++) {
            const int kb = ks * 16;
            uint32_t af[4], bfr[4];
            ldsm4(af, ap + 2u * ((wm * 16 + aRow) * VP + kb + aK));
            ldsm4(bfr, bv + 2u * ((wn * 16 + bRow) * VP + kb + bK));
            #pragma unroll
            for (int nt = 0; nt < 2; nt++)
                mma_f16(o[nt], af, &bfr[nt * 2]);
        }
    }

    // ---- epilogue: write bf16 hi/lo ----
    #pragma unroll
    for (int nt = 0; nt < 2; nt++) {
        int rl = wm * 16 + g;
        int d  = wn * 16 + nt * 8 + 2 * t;
        #pragma unroll
        for (int half_i = 0; half_i < 2; half_i++) {
            int row = rl + half_i * 8;
            float v0 = o[nt][half_i * 2 + 0];
            float v1 = o[nt][half_i * 2 + 1];
            __nv_bfloat16 h0 = __float2bfloat16(v0);
            __nv_bfloat16 h1 = __float2bfloat16(v1);
            size_t off = (size_t)(b * SQ + q0 + row) * DD + h * 64 + d;
            *(__nv_bfloat162*)(g_ah + off) = __nv_bfloat162(h0, h1);
            *(__nv_bfloat162*)(g_al + off) = __floats2bfloat162_rn(
                v0 - __bfloat162float(h0), v1 - __bfloat162float(h1));
        }
    }
}

// ============================================================
// Launch
// ============================================================
extern "C" void kernel_launch(void* const* d_in, const int* in_sizes, int n_in,
                              void* d_out, int out_size)
{
    const float* x    = (const float*)d_in[0];
    const float* traj = (const float*)d_in[1];
    const float* Wqkv = (const float*)d_in[3];
    const float* Wout = (const float*)d_in[4];
    float* out = (float*)d_out;

    void* p;
    cudaGetSymbolAddress(&p, g_qkv);  float* qkv = (float*)p;
    cudaGetSymbolAddress(&p, g_xh);   __nv_bfloat16* xh = (__nv_bfloat16*)p;
    cudaGetSymbolAddress(&p, g_xl);   __nv_bfloat16* xl = (__nv_bfloat16*)p;
    cudaGetSymbolAddress(&p, g_ah);   __nv_bfloat16* ah = (__nv_bfloat16*)p;
    cudaGetSymbolAddress(&p, g_al);   __nv_bfloat16* al = (__nv_bfloat16*)p;
    cudaGetSymbolAddress(&p, g_wqh);  __nv_bfloat16* wqh = (__nv_bfloat16*)p;
    cudaGetSymbolAddress(&p, g_wql);  __nv_bfloat16* wql = (__nv_bfloat16*)p;
    cudaGetSymbolAddress(&p, g_woh);  __nv_bfloat16* woh = (__nv_bfloat16*)p;
    cudaGetSymbolAddress(&p, g_wol);  __nv_bfloat16* wol = (__nv_bfloat16*)p;

    // split x
    {
        int n4 = MTOK * DD / 4;
        split_kernel<<<(n4 + 255) / 256, 256>>>(
            (const float4*)x, (__nv_bfloat162*)xh, (__nv_bfloat162*)xl, n4);
    }
    // transpose+split weights
    {
        dim3 grid(3072 / 32, DD / 32);
        tsplit_kernel<<<grid, dim3(32, 8)>>>(Wqkv, wqh, wql, DD, 3072);
    }
    {
        dim3 grid(DD / 32, DD / 32);
        tsplit_kernel<<<grid, dim3(32, 8)>>>(Wout, woh, wol, DD, DD);
    }
    // GEMM1: qkv = x @ W_qkv
    {
        cudaFuncSetAttribute(gemm_bf16x3,
            cudaFuncAttributeMaxDynamicSharedMemorySize, GEMM_SMEM);
        dim3 grid(3072 / 128, MTOK / 256);
        gemm_bf16x3<<<grid, 512, GEMM_SMEM>>>(xh, xl, wqh, wql, qkv, MTOK, 3072, DD);
    }
    // attention
    {
        cudaFuncSetAttribute(attn_kernel,
            cudaFuncAttributeMaxDynamicSharedMemorySize, ATTN_SMEM);
        dim3 grid(SQ / 64, NH, BB);
        attn_kernel<<<grid, 512, ATTN_SMEM>>>(traj);
    }
    // GEMM2: out = att @ W_out
    {
        dim3 grid(DD / 128, MTOK / 256);
        gemm_bf16x3<<<grid, 512, GEMM_SMEM>>>(ah, al, woh, wol, out, MTOK, DD, DD);
    }
}